// round 13
// baseline (speedup 1.0000x reference)
#include <cuda_runtime.h>
#include <cuda_fp16.h>
#include <math.h>
#include <stdint.h>

// Problem constants
#define Bq   2
#define Sq   2048
#define DIMq 2048
#define Hq   16
#define DKq  128
#define DRq  64
#define DCq  512
#define DCPq 1024
#define DVq  128
#define DQK  192
#define Mrows (Bq*Sq)      // 4096

// ------------------------- scratch arena (bss) ------------------------------
#define O_XHI    0ULL
#define O_XLO    16777216ULL
#define O_WXT    33554432ULL      // packed [1664][2048]: c[0,512) cp[512,1536) kr[1536,1600) pad
#define O_WQT    40370176ULL      // packed [16][192][1024]
#define O_WKVT   46661632ULL      // packed [16][256][512]
#define O_CC     50855936ULL      // cc single fp16 [4096][1536]
#define O_QH     63438848ULL      // q single [B,H,S,192]
#define O_KC     88604672ULL      // k_c single [B,H,S,128]
#define O_VS     105381888ULL     // v single [B,H,S,128]
#define O_KR     122159104ULL     // kr single [B,S,64] (shared across heads)
#define ARENA_BYTES 122683392ULL

__device__ __align__(256) char g_arena[ARENA_BYTES];

// ------------------------- helpers ------------------------------------------
__device__ __forceinline__ uint32_t smem_u32(const void* p) {
    uint32_t a;
    asm("{ .reg .u64 t; cvta.to.shared.u64 t, %1; cvt.u32.u64 %0, t; }" : "=r"(a) : "l"(p));
    return a;
}

__device__ __forceinline__ void cp16(uint32_t dst, const void* src) {
    asm volatile("cp.async.cg.shared.global [%0], [%1], 16;" :: "r"(dst), "l"(src));
}
#define CP_COMMIT() asm volatile("cp.async.commit_group;" ::: "memory")
#define CP_WAIT(n)  asm volatile("cp.async.wait_group %0;" :: "n"(n) : "memory")

__device__ __forceinline__ void ldm4(uint32_t* r, uint32_t addr) {
    asm volatile("ldmatrix.sync.aligned.m8n8.x4.shared.b16 {%0,%1,%2,%3}, [%4];"
                 : "=r"(r[0]), "=r"(r[1]), "=r"(r[2]), "=r"(r[3]) : "r"(addr));
}
__device__ __forceinline__ void ldm4t(uint32_t* r, uint32_t addr) {
    asm volatile("ldmatrix.sync.aligned.m8n8.x4.trans.shared.b16 {%0,%1,%2,%3}, [%4];"
                 : "=r"(r[0]), "=r"(r[1]), "=r"(r[2]), "=r"(r[3]) : "r"(addr));
}

__device__ __forceinline__ void mma16816(float* d, const uint32_t* a, const uint32_t* b) {
    asm volatile("mma.sync.aligned.m16n8k16.row.col.f32.f16.f16.f32 "
                 "{%0,%1,%2,%3}, {%4,%5,%6,%7}, {%8,%9}, {%0,%1,%2,%3};"
                 : "+f"(d[0]), "+f"(d[1]), "+f"(d[2]), "+f"(d[3])
                 : "r"(a[0]), "r"(a[1]), "r"(a[2]), "r"(a[3]), "r"(b[0]), "r"(b[1]));
}

__device__ __forceinline__ uint32_t packh2(float x, float y) {
    __half2 t = __floats2half2_rn(x, y);
    return *(uint32_t*)&t;
}

// ---------------------------------------------------------------------------
// split x fp32 -> fp16 hi/lo
// ---------------------------------------------------------------------------
__global__ __launch_bounds__(256)
void split_f32(const float* __restrict__ A, __half* __restrict__ hi,
               __half* __restrict__ lo)
{
    int i = blockIdx.x * 256 + threadIdx.x;
    float v = A[i];
    __half h = __float2half_rn(v);
    hi[i] = h;
    lo[i] = __float2half_rn(v - __half2float(h));
}

// ---------------------------------------------------------------------------
// One kernel for ALL weight transposes+roundings (8320 tiles of 32x32).
// ---------------------------------------------------------------------------
__device__ __forceinline__ void tr_tile(const float* __restrict__ W,
                                        __half* __restrict__ out,
                                        int K, int N, int bx, int by)
{
    __shared__ float t[32][33];
    const int k0 = by * 32, n0 = bx * 32;
    const int x = threadIdx.x & 31, y = threadIdx.x >> 5;
#pragma unroll
    for (int i = 0; i < 4; i++)
        t[y + 8*i][x] = W[(size_t)(k0 + y + 8*i) * N + n0 + x];
    __syncthreads();
#pragma unroll
    for (int i = 0; i < 4; i++)
        out[(size_t)(n0 + y + 8*i) * K + k0 + x] = __float2half_rn(t[x][y + 8*i]);
}

__global__ __launch_bounds__(256)
void tround_all(const float* __restrict__ W_c, const float* __restrict__ W_cp,
                const float* __restrict__ W_qc, const float* __restrict__ W_qr,
                const float* __restrict__ W_kc, const float* __restrict__ W_v,
                const float* __restrict__ W_kr,
                __half* __restrict__ WxT, __half* __restrict__ WqT,
                __half* __restrict__ WkvT)
{
    const int bid = blockIdx.x;
    if (bid < 1024) {                       // W_c -> WxT rows [0,512)
        tr_tile(W_c, WxT, 2048, 512, bid & 15, bid >> 4);
    } else if (bid < 3072) {                // W_cp -> WxT rows [512,1536)
        int l = bid - 1024;
        tr_tile(W_cp, WxT + (size_t)512 * 2048, 2048, 1024, l & 31, l >> 5);
    } else if (bid < 5120) {                // W_qc
        int l = bid - 3072;
        int h = l >> 7, rem = l & 127;
        tr_tile(W_qc + (size_t)h * 1024 * 128, WqT + (size_t)h * 192 * 1024,
                1024, 128, rem & 3, rem >> 2);
    } else if (bid < 6144) {                // W_qr
        int l = bid - 5120;
        int h = l >> 6, rem = l & 63;
        tr_tile(W_qr + (size_t)h * 1024 * 64, WqT + (size_t)h * 192 * 1024 + 128 * 1024,
                1024, 64, rem & 1, rem >> 1);
    } else if (bid < 7168) {                // W_kc
        int l = bid - 6144;
        int h = l >> 6, rem = l & 63;
        tr_tile(W_kc + (size_t)h * 512 * 128, WkvT + (size_t)h * 256 * 512,
                512, 128, rem & 3, rem >> 2);
    } else if (bid < 8192) {                // W_v
        int l = bid - 7168;
        int h = l >> 6, rem = l & 63;
        tr_tile(W_v + (size_t)h * 512 * 128, WkvT + (size_t)h * 256 * 512 + 128 * 512,
                512, 128, rem & 3, rem >> 2);
    } else {                                // W_kr -> WxT rows [1536,1600)
        int l = bid - 8192;
        tr_tile(W_kr, WxT + (size_t)1536 * 2048, 2048, 64, l & 1, l >> 1);
    }
}

// ---------------------------------------------------------------------------
// mma.sync fp16 GEMM: C = (Ahi [+ Alo]) * W16. TERMS = 1 or 2.
// k=32 chunks, ROWB=80 (conflict-free), NSTAGES-deep cp.async pipeline,
// occupancy 2. A row stride = Astride.
// out_kind: 4 = fp16 single per-head, out_ld stride, col_off
//           6 = kv split: col<128 -> C1 [B,H,S,128]; col>=128 -> Chi [B,H,S,128]
//           8 = fused cc+kr: col<1536 -> Chi [M][1536] single;
//               1536<=col<1600 -> C1 [M][64]; col>=1600 -> discard
// ---------------------------------------------------------------------------
template<int BN, int TERMS, int NSTAGES>
__global__ __launch_bounds__(256, 2)
void mma_gemm(const __half* __restrict__ Ahi, const __half* __restrict__ Alo,
              const __half* __restrict__ Bw,
              __half* __restrict__ C1, __half* __restrict__ Chi,
              int K, int Astride, int Nfull, int out_kind, int col_off, int out_ld)
{
    constexpr int ROWB = 80;            // 64 B data + 16 B pad
    constexpr int ABUF = 128 * ROWB;    // 10240 B
    constexpr int BBUF = BN * ROWB;
    constexpr int BUFSZ = TERMS * ABUF + BBUF;
    constexpr int BNW  = BN / 2;
    constexpr int NFR  = BNW / 8;

    extern __shared__ __align__(16) char smg[];

    const int tid  = threadIdx.x;
    const int wid  = tid >> 5;
    const int lane = tid & 31;
    const int m_blk = blockIdx.y * 128;
    const int n_blk = blockIdx.x * BN;
    const int head  = blockIdx.z;
    const int warp_m = (wid >> 1) * 32;
    const int warp_n = (wid & 1) * BNW;

    const __half* Bp = Bw + (size_t)head * (size_t)Nfull * (size_t)K;

    const uint32_t sb = smem_u32(smg);
    const int KC = K >> 5;

    float acc[2][NFR][4];
#pragma unroll
    for (int mi = 0; mi < 2; mi++)
#pragma unroll
        for (int ni = 0; ni < NFR; ni++)
#pragma unroll
            for (int j = 0; j < 4; j++) acc[mi][ni][j] = 0.f;

    auto load_chunk = [&](int i, int buf) {
        const int kt = i << 5;
        const uint32_t db = sb + buf * BUFSZ;
#pragma unroll
        for (int j = 0; j < 2; j++) {
            int e = tid + j * 256;          // 0..511
            int r = e >> 2, s = e & 3;
            size_t g = (size_t)(m_blk + r) * Astride + kt + s * 8;
            cp16(db + r * ROWB + s * 16, Ahi + g);
            if (TERMS == 2)
                cp16(db + ABUF + r * ROWB + s * 16, Alo + g);
        }
#pragma unroll
        for (int j = 0; j < BN / 64; j++) {
            int e = tid + j * 256;
            int r = e >> 2, s = e & 3;
            cp16(db + TERMS * ABUF + r * ROWB + s * 16,
                 Bp + (size_t)(n_blk + r) * K + kt + s * 8);
        }
        CP_COMMIT();
    };

    // prologue: fill NSTAGES-1 buffers
#pragma unroll
    for (int s = 0; s < NSTAGES - 1; s++)
        load_chunk(s, s);

    const uint32_t aoff = (uint32_t)((warp_m + (lane & 15)) * ROWB + ((lane >> 4) << 4));
    const uint32_t boff = (uint32_t)((warp_n + (lane & 7) + ((lane >> 4) << 3)) * ROWB +
                                     (((lane >> 3) & 1) << 4));

    for (int i = 0; i < KC; i++) {
        // always commit exactly one group per iteration so CP_WAIT counts stay exact
        if (i + NSTAGES - 1 < KC) {
            load_chunk(i + NSTAGES - 1, (i + NSTAGES - 1) % NSTAGES);
        } else {
            CP_COMMIT();
        }
        CP_WAIT(NSTAGES - 1);
        __syncthreads();

        const uint32_t db = sb + (i % NSTAGES) * BUFSZ;
#pragma unroll
        for (int ks = 0; ks < 2; ks++) {
            uint32_t ah[2][4], al[2][4];
#pragma unroll
            for (int mi = 0; mi < 2; mi++) {
                ldm4(ah[mi], db + aoff + mi * 16 * ROWB + ks * 32);
                if (TERMS == 2)
                    ldm4(al[mi], db + ABUF + aoff + mi * 16 * ROWB + ks * 32);
            }
            uint32_t b[NFR][2];
#pragma unroll
            for (int nj = 0; nj < NFR / 2; nj++) {
                uint32_t r[4];
                ldm4(r, db + TERMS * ABUF + boff + nj * 16 * ROWB + ks * 32);
                b[2*nj][0] = r[0]; b[2*nj][1] = r[1];
                b[2*nj+1][0] = r[2]; b[2*nj+1][1] = r[3];
            }
#pragma unroll
            for (int mi = 0; mi < 2; mi++)
#pragma unroll
                for (int ni = 0; ni < NFR; ni++) {
                    mma16816(acc[mi][ni], ah[mi], b[ni]);
                    if (TERMS == 2)
                        mma16816(acc[mi][ni], al[mi], b[ni]);
                }
        }
        __syncthreads();
    }

    const int g = lane >> 2, c2 = (lane & 3) * 2;
#pragma unroll
    for (int mi = 0; mi < 2; mi++) {
#pragma unroll
        for (int ni = 0; ni < NFR; ni++) {
            int col = n_blk + warp_n + ni * 8 + c2;
#pragma unroll
            for (int hrow = 0; hrow < 2; hrow++) {
                int m = m_blk + warp_m + mi * 16 + g + hrow * 8;
                float v0 = acc[mi][ni][hrow * 2];
                float v1 = acc[mi][ni][hrow * 2 + 1];
                if (out_kind == 8) {
                    if (col < 1536)
                        *(uint32_t*)(Chi + (size_t)m * 1536 + col) = packh2(v0, v1);
                    else if (col < 1600)
                        *(uint32_t*)(C1 + (size_t)m * 64 + col - 1536) = packh2(v0, v1);
                } else if (out_kind == 4) {
                    int b = m >> 11, s = m & 2047;
                    size_t o = ((size_t)((b * Hq + head) * Sq + s)) * out_ld + col_off + col;
                    *(uint32_t*)(C1 + o) = packh2(v0, v1);
                } else if (out_kind == 6) {
                    int b = m >> 11, s = m & 2047;
                    size_t rowb = (size_t)((b * Hq + head) * Sq + s);
                    if (col < 128)
                        *(uint32_t*)(C1 + rowb * 128 + col) = packh2(v0, v1);
                    else
                        *(uint32_t*)(Chi + rowb * 128 + col - 128) = packh2(v0, v1);
                }
            }
        }
    }
}

// ---------------------------------------------------------------------------
// Causal flash attention, fp16 operands, fp32 accum.
// K tile assembled in the loader from per-head k_c (cols 0-127) and the
// head-shared kr buffer (cols 128-191). grid (S/128, B*H), 256 threads.
// ---------------------------------------------------------------------------
#define QSTRB 400   // 192 fp16 = 384 B + 16 pad
#define VSTRB 272   // 128 fp16 = 256 B + 16 pad
#define KBUF0 51200          // 2 x 25600 (K assembled)
#define VBUF0 102400         // 2 x 17408 (V)
#define ATTN_SMEM 137216

__global__ __launch_bounds__(256, 1)
void attn_mma(const __half* __restrict__ q_,
              const __half* __restrict__ kc_, const __half* __restrict__ kr_,
              const __half* __restrict__ v_, float* __restrict__ O)
{
    extern __shared__ __align__(16) char sm[];
    const uint32_t sb = smem_u32(sm);

    const int bh = blockIdx.y;
    const int b = bh >> 4, h = bh & 15;
    const int s0 = ((int)gridDim.x - 1 - (int)blockIdx.x) * 128;
    const int tid = threadIdx.x, wid = tid >> 5, lane = tid & 31;
    const int warp_m = wid * 16;
    const int g = lane >> 2, c2 = (lane & 3) * 2;

    const size_t qb  = (size_t)bh * Sq * DQK;
    const size_t kcb = (size_t)bh * Sq * DKq;
    const size_t krb = (size_t)b * Sq * DRq;
    const size_t vb  = (size_t)bh * Sq * DVq;

    const uint32_t a_off = (uint32_t)((warp_m + (lane & 15)) * QSTRB + ((lane >> 4) << 4));
    const uint32_t b_off = (uint32_t)(((lane & 7) + ((lane >> 4) << 3)) * QSTRB +
                                      (((lane >> 3) & 1) << 4));
    const uint32_t v_off = (uint32_t)((lane & 15) * VSTRB + ((lane >> 4) << 4));

    // ---- stage Q (resident) ----
    {
        const __half* sh = q_ + qb + (size_t)s0 * DQK;
#pragma unroll
        for (int j = 0; j < 12; j++) {
            int e = tid + j * 256;            // 0..3071
            int r = e / 24, s = e - r * 24;
            cp16(sb + r * QSTRB + s * 16, sh + r * 192 + s * 8);
        }
        CP_COMMIT();
    }

    // ---- K/V tile loader: K = [k_c | kr] ----
    auto load_kv = [&](int jb, int buf) {
        const uint32_t kb = sb + KBUF0 + buf * 25600;
        const uint32_t vbuf = sb + VBUF0 + buf * 17408;
        const __half* skc = kc_ + kcb + (size_t)(jb * 64) * DKq;
        const __half* skr = kr_ + krb + (size_t)(jb * 64) * DRq;
        const __half* sv  = v_ + vb + (size_t)(jb * 64) * DVq;
#pragma unroll
        for (int j = 0; j < 6; j++) {
            int e = tid + j * 256;            // 0..1535 = 64 rows x 24 segs
            int r = e / 24, s = e - r * 24;
            if (s < 16)
                cp16(kb + r * QSTRB + s * 16, skc + r * 128 + s * 8);
            else
                cp16(kb + r * QSTRB + s * 16, skr + r * 64 + (s - 16) * 8);
        }
#pragma unroll
        for (int j = 0; j < 4; j++) {
            int e = tid + j * 256;            // 0..1023
            int r = e >> 4, s = e & 15;
            cp16(vbuf + r * VSTRB + s * 16, sv + r * 128 + s * 8);
        }
        CP_COMMIT();
    };

    const int jmax = (s0 >> 6) + 1;
    load_kv(0, 0);

    float accO[16][4];
#pragma unroll
    for (int nf = 0; nf < 16; nf++)
#pragma unroll
        for (int j = 0; j < 4; j++) accO[nf][j] = 0.f;
    float m0 = -INFINITY, m1 = -INFINITY, l0 = 0.f, l1 = 0.f;

    const float scale = 0.07216878364870322f;   // 1/sqrt(192)
    const int row0 = s0 + warp_m + g;
    const int row1 = row0 + 8;

    for (int jb = 0; jb <= jmax; jb++) {
        const int buf = jb & 1;
        if (jb < jmax) {
            load_kv(jb + 1, buf ^ 1);
            CP_WAIT(1);
        } else {
            CP_WAIT(0);
        }
        __syncthreads();

        const uint32_t kb = sb + KBUF0 + buf * 25600;
        const uint32_t vbuf = sb + VBUF0 + buf * 17408;

        // ---- S = Q K^T ----
        float S[8][4];
#pragma unroll
        for (int nf = 0; nf < 8; nf++)
#pragma unroll
            for (int j = 0; j < 4; j++) S[nf][j] = 0.f;

#pragma unroll
        for (int ks = 0; ks < 12; ks++) {
            uint32_t ah[4];
            ldm4(ah, sb + a_off + ks * 32);
#pragma unroll
            for (int p = 0; p < 4; p++) {
                uint32_t bv[4];
                ldm4(bv, kb + b_off + p * 16 * QSTRB + ks * 32);
                mma16816(S[2*p],   ah, bv);
                mma16816(S[2*p+1], ah, bv + 2);
            }
        }

        // ---- scale + causal mask ----
        const bool domask = ((jb << 6) + 63) > row0;
#pragma unroll
        for (int nf = 0; nf < 8; nf++) {
#pragma unroll
            for (int j = 0; j < 4; j++) S[nf][j] *= scale;
            if (domask) {
                int key0 = (jb << 6) + nf * 8 + c2;
                if (key0     > row0) S[nf][0] = -INFINITY;
                if (key0 + 1 > row0) S[nf][1] = -INFINITY;
                if (key0     > row1) S[nf][2] = -INFINITY;
                if (key0 + 1 > row1) S[nf][3] = -INFINITY;
            }
        }

        // ---- online softmax ----
        float rm0 = -INFINITY, rm1 = -INFINITY;
#pragma unroll
        for (int nf = 0; nf < 8; nf++) {
            rm0 = fmaxf(rm0, fmaxf(S[nf][0], S[nf][1]));
            rm1 = fmaxf(rm1, fmaxf(S[nf][2], S[nf][3]));
        }
        rm0 = fmaxf(rm0, __shfl_xor_sync(0xffffffffu, rm0, 1));
        rm0 = fmaxf(rm0, __shfl_xor_sync(0xffffffffu, rm0, 2));
        rm1 = fmaxf(rm1, __shfl_xor_sync(0xffffffffu, rm1, 1));
        rm1 = fmaxf(rm1, __shfl_xor_sync(0xffffffffu, rm1, 2));

        float mn0 = fmaxf(m0, rm0), mn1 = fmaxf(m1, rm1);
        float al0 = __expf(m0 - mn0), al1 = __expf(m1 - mn1);
        m0 = mn0; m1 = mn1;

        float rs0 = 0.f, rs1 = 0.f;
#pragma unroll
        for (int nf = 0; nf < 8; nf++) {
            S[nf][0] = __expf(S[nf][0] - mn0);
            S[nf][1] = __expf(S[nf][1] - mn0);
            S[nf][2] = __expf(S[nf][2] - mn1);
            S[nf][3] = __expf(S[nf][3] - mn1);
            rs0 += S[nf][0] + S[nf][1];
            rs1 += S[nf][2] + S[nf][3];
        }
        rs0 += __shfl_xor_sync(0xffffffffu, rs0, 1);
        rs0 += __shfl_xor_sync(0xffffffffu, rs0, 2);
        rs1 += __shfl_xor_sync(0xffffffffu, rs1, 1);
        rs1 += __shfl_xor_sync(0xffffffffu, rs1, 2);
        l0 = l0 * al0 + rs0;
        l1 = l1 * al1 + rs1;

#pragma unroll
        for (int nf = 0; nf < 16; nf++) {
            accO[nf][0] *= al0; accO[nf][1] *= al0;
            accO[nf][2] *= al1; accO[nf][3] *= al1;
        }

        // ---- pack P fragments (single fp16) ----
        uint32_t ph[4][4];
#pragma unroll
        for (int t = 0; t < 4; t++) {
            ph[t][0] = packh2(S[2*t][0],   S[2*t][1]);
            ph[t][1] = packh2(S[2*t][2],   S[2*t][3]);
            ph[t][2] = packh2(S[2*t+1][0], S[2*t+1][1]);
            ph[t][3] = packh2(S[2*t+1][2], S[2*t+1][3]);
        }

        // ---- O += P V ----
#pragma unroll
        for (int t = 0; t < 4; t++) {
#pragma unroll
            for (int p = 0; p < 8; p++) {
                uint32_t bv[4];
                ldm4t(bv, vbuf + v_off + t * 16 * VSTRB + p * 32);
                mma16816(accO[2*p],   ph[t], bv);
                mma16816(accO[2*p+1], ph[t], bv + 2);
            }
        }
        __syncthreads();
    }

    // ---- epilogue ----
    float inv0 = 1.0f / l0, inv1 = 1.0f / l1;
#pragma unroll
    for (int nf = 0; nf < 16; nf++) {
        int col = h * DVq + nf * 8 + c2;
        size_t o0 = ((size_t)(b * Sq + row0)) * (size_t)(Hq * DVq) + col;
        size_t o1 = ((size_t)(b * Sq + row1)) * (size_t)(Hq * DVq) + col;
        *(float2*)(O + o0) = make_float2(accO[nf][0] * inv0, accO[nf][1] * inv0);
        *(float2*)(O + o1) = make_float2(accO[nf][2] * inv1, accO[nf][3] * inv1);
    }
}

// ---------------------------------------------------------------------------
extern "C" void kernel_launch(void* const* d_in, const int* in_sizes, int n_in,
                              void* d_out, int out_size)
{
    (void)in_sizes; (void)n_in; (void)out_size;
    const float* x    = (const float*)d_in[0];
    const float* W_c  = (const float*)d_in[1];
    const float* W_cp = (const float*)d_in[2];
    const float* W_qc = (const float*)d_in[3];
    const float* W_qr = (const float*)d_in[4];
    const float* W_kc = (const float*)d_in[5];
    const float* W_kr = (const float*)d_in[6];
    const float* W_v  = (const float*)d_in[7];
    float* out = (float*)d_out;

    char* arena;
    cudaGetSymbolAddress((void**)&arena, g_arena);
    __half* xhi   = (__half*)(arena + O_XHI);
    __half* xlo   = (__half*)(arena + O_XLO);
    __half* WxT   = (__half*)(arena + O_WXT);
    __half* WqT   = (__half*)(arena + O_WQT);
    __half* WkvT  = (__half*)(arena + O_WKVT);
    __half* cc    = (__half*)(arena + O_CC);
    __half* qh    = (__half*)(arena + O_QH);
    __half* kc    = (__half*)(arena + O_KC);
    __half* vs    = (__half*)(arena + O_VS);
    __half* kr    = (__half*)(arena + O_KR);

    const int GSM_CC = 2 * (2 * 10240 + 128 * 80);  // 61440: TERMS=2, 2 stages
    const int GSM_Q  = 4 * (1 * 10240 +  64 * 80);  // 61440: TERMS=1, 4 stages
    const int GSM_KV = 3 * (1 * 10240 + 128 * 80);  // 61440: TERMS=1, 3 stages
    cudaFuncSetAttribute((const void*)mma_gemm<128,2,2>, cudaFuncAttributeMaxDynamicSharedMemorySize, GSM_CC);
    cudaFuncSetAttribute((const void*)mma_gemm<64,1,4>,  cudaFuncAttributeMaxDynamicSharedMemorySize, GSM_Q);
    cudaFuncSetAttribute((const void*)mma_gemm<128,1,3>, cudaFuncAttributeMaxDynamicSharedMemorySize, GSM_KV);
    cudaFuncSetAttribute(attn_mma, cudaFuncAttributeMaxDynamicSharedMemorySize, ATTN_SMEM);

    // prep: x split + all weight transposes in one kernel
    split_f32<<<32768, 256>>>(x, xhi, xlo);
    tround_all<<<8320, 256>>>(W_c, W_cp, W_qc, W_qr, W_kc, W_v, W_kr,
                              WxT, WqT, WkvT);

    // fused c+cp+kr projection (2-term from x), cc stored single fp16
    mma_gemm<128,2,2><<<dim3(13, 32, 1), 256, GSM_CC>>>(xhi, xlo, WxT, kr, cc,
                                                        2048, 2048, 1664, 8, 0, 0);
    // q projection (1-term from cc's cp half), 4-stage pipeline
    mma_gemm<64,1,4> <<<dim3(3, 32, 16), 256, GSM_Q >>>(cc + 512, nullptr, WqT,
                                                        qh, nullptr,
                                                        1024, 1536, 192, 4, 0, DQK);
    // k_c + v projection (1-term from cc's c half), 3-stage pipeline
    mma_gemm<128,1,3><<<dim3(2, 32, 16), 256, GSM_KV>>>(cc, nullptr, WkvT, kc, vs,
                                                        512, 1536, 256, 6, 0, 0);

    attn_mma<<<dim3(Sq / 128, Bq * Hq), 256, ATTN_SMEM>>>(qh, kc, kr, vs, out);
}

// round 14
// speedup vs baseline: 1.0413x; 1.0413x over previous
#include <cuda_runtime.h>
#include <cuda_fp16.h>
#include <math.h>
#include <stdint.h>

// Problem constants
#define Bq   2
#define Sq   2048
#define DIMq 2048
#define Hq   16
#define DKq  128
#define DRq  64
#define DCq  512
#define DCPq 1024
#define DVq  128
#define DQK  192
#define Mrows (Bq*Sq)      // 4096

// ------------------------- scratch arena (bss) ------------------------------
#define O_XHI    0ULL
#define O_XLO    16777216ULL
#define O_WXT    33554432ULL      // packed [1664][2048]: c[0,512) cp[512,1536) kr[1536,1600) pad
#define O_WQT    40370176ULL      // packed [16][192][1024]
#define O_WKVT   46661632ULL      // packed [16][256][512]
#define O_CC     50855936ULL      // cc single fp16 [4096][1536]
#define O_QH     63438848ULL      // q single [B,H,S,192]
#define O_KC     88604672ULL      // k_c single [B,H,S,128]
#define O_VS     105381888ULL     // v single [B,H,S,128]
#define O_KR     122159104ULL     // kr single [B,S,64] (shared across heads)
#define ARENA_BYTES 122683392ULL

__device__ __align__(256) char g_arena[ARENA_BYTES];

// ------------------------- helpers ------------------------------------------
__device__ __forceinline__ uint32_t smem_u32(const void* p) {
    uint32_t a;
    asm("{ .reg .u64 t; cvta.to.shared.u64 t, %1; cvt.u32.u64 %0, t; }" : "=r"(a) : "l"(p));
    return a;
}

__device__ __forceinline__ void cp16(uint32_t dst, const void* src) {
    asm volatile("cp.async.cg.shared.global [%0], [%1], 16;" :: "r"(dst), "l"(src));
}
#define CP_COMMIT() asm volatile("cp.async.commit_group;" ::: "memory")
#define CP_WAIT(n)  asm volatile("cp.async.wait_group %0;" :: "n"(n) : "memory")

__device__ __forceinline__ void ldm4(uint32_t* r, uint32_t addr) {
    asm volatile("ldmatrix.sync.aligned.m8n8.x4.shared.b16 {%0,%1,%2,%3}, [%4];"
                 : "=r"(r[0]), "=r"(r[1]), "=r"(r[2]), "=r"(r[3]) : "r"(addr));
}
__device__ __forceinline__ void ldm4t(uint32_t* r, uint32_t addr) {
    asm volatile("ldmatrix.sync.aligned.m8n8.x4.trans.shared.b16 {%0,%1,%2,%3}, [%4];"
                 : "=r"(r[0]), "=r"(r[1]), "=r"(r[2]), "=r"(r[3]) : "r"(addr));
}

__device__ __forceinline__ void mma16816(float* d, const uint32_t* a, const uint32_t* b) {
    asm volatile("mma.sync.aligned.m16n8k16.row.col.f32.f16.f16.f32 "
                 "{%0,%1,%2,%3}, {%4,%5,%6,%7}, {%8,%9}, {%0,%1,%2,%3};"
                 : "+f"(d[0]), "+f"(d[1]), "+f"(d[2]), "+f"(d[3])
                 : "r"(a[0]), "r"(a[1]), "r"(a[2]), "r"(a[3]), "r"(b[0]), "r"(b[1]));
}

__device__ __forceinline__ uint32_t packh2(float x, float y) {
    __half2 t = __floats2half2_rn(x, y);
    return *(uint32_t*)&t;
}

// ---------------------------------------------------------------------------
// split x fp32 -> fp16 hi/lo
// ---------------------------------------------------------------------------
__global__ __launch_bounds__(256)
void split_f32(const float* __restrict__ A, __half* __restrict__ hi,
               __half* __restrict__ lo)
{
    int i = blockIdx.x * 256 + threadIdx.x;
    float v = A[i];
    __half h = __float2half_rn(v);
    hi[i] = h;
    lo[i] = __float2half_rn(v - __half2float(h));
}

// ---------------------------------------------------------------------------
// One kernel for ALL weight transposes+roundings (8320 tiles of 32x32).
// ---------------------------------------------------------------------------
__device__ __forceinline__ void tr_tile(const float* __restrict__ W,
                                        __half* __restrict__ out,
                                        int K, int N, int bx, int by)
{
    __shared__ float t[32][33];
    const int k0 = by * 32, n0 = bx * 32;
    const int x = threadIdx.x & 31, y = threadIdx.x >> 5;
#pragma unroll
    for (int i = 0; i < 4; i++)
        t[y + 8*i][x] = W[(size_t)(k0 + y + 8*i) * N + n0 + x];
    __syncthreads();
#pragma unroll
    for (int i = 0; i < 4; i++)
        out[(size_t)(n0 + y + 8*i) * K + k0 + x] = __float2half_rn(t[x][y + 8*i]);
}

__global__ __launch_bounds__(256)
void tround_all(const float* __restrict__ W_c, const float* __restrict__ W_cp,
                const float* __restrict__ W_qc, const float* __restrict__ W_qr,
                const float* __restrict__ W_kc, const float* __restrict__ W_v,
                const float* __restrict__ W_kr,
                __half* __restrict__ WxT, __half* __restrict__ WqT,
                __half* __restrict__ WkvT)
{
    const int bid = blockIdx.x;
    if (bid < 1024) {                       // W_c -> WxT rows [0,512)
        tr_tile(W_c, WxT, 2048, 512, bid & 15, bid >> 4);
    } else if (bid < 3072) {                // W_cp -> WxT rows [512,1536)
        int l = bid - 1024;
        tr_tile(W_cp, WxT + (size_t)512 * 2048, 2048, 1024, l & 31, l >> 5);
    } else if (bid < 5120) {                // W_qc
        int l = bid - 3072;
        int h = l >> 7, rem = l & 127;
        tr_tile(W_qc + (size_t)h * 1024 * 128, WqT + (size_t)h * 192 * 1024,
                1024, 128, rem & 3, rem >> 2);
    } else if (bid < 6144) {                // W_qr
        int l = bid - 5120;
        int h = l >> 6, rem = l & 63;
        tr_tile(W_qr + (size_t)h * 1024 * 64, WqT + (size_t)h * 192 * 1024 + 128 * 1024,
                1024, 64, rem & 1, rem >> 1);
    } else if (bid < 7168) {                // W_kc
        int l = bid - 6144;
        int h = l >> 6, rem = l & 63;
        tr_tile(W_kc + (size_t)h * 512 * 128, WkvT + (size_t)h * 256 * 512,
                512, 128, rem & 3, rem >> 2);
    } else if (bid < 8192) {                // W_v
        int l = bid - 7168;
        int h = l >> 6, rem = l & 63;
        tr_tile(W_v + (size_t)h * 512 * 128, WkvT + (size_t)h * 256 * 512 + 128 * 512,
                512, 128, rem & 3, rem >> 2);
    } else {                                // W_kr -> WxT rows [1536,1600)
        int l = bid - 8192;
        tr_tile(W_kr, WxT + (size_t)1536 * 2048, 2048, 64, l & 1, l >> 1);
    }
}

// ---------------------------------------------------------------------------
// cc GEMM (TERMS=2): C = (Ahi+Alo) * W16. k=32 chunks, ROWB=80, 2 stages,
// occupancy 2. out_kind 8 only: col<1536 -> Chi [M][1536]; 1536..1600 -> C1.
// ---------------------------------------------------------------------------
__global__ __launch_bounds__(256, 2)
void cc_gemm(const __half* __restrict__ Ahi, const __half* __restrict__ Alo,
             const __half* __restrict__ Bw,
             __half* __restrict__ C1, __half* __restrict__ Chi, int K)
{
    constexpr int ROWB = 80;
    constexpr int ABUF = 128 * ROWB;    // 10240
    constexpr int BBUF = 128 * ROWB;
    constexpr int BUFSZ = 2 * ABUF + BBUF;
    constexpr int NFR  = 8;             // 64 cols per warp

    extern __shared__ __align__(16) char smg[];

    const int tid  = threadIdx.x;
    const int wid  = tid >> 5;
    const int lane = tid & 31;
    const int m_blk = blockIdx.y * 128;
    const int n_blk = blockIdx.x * 128;
    const int warp_m = (wid >> 1) * 32;
    const int warp_n = (wid & 1) * 64;

    const uint32_t sb = smem_u32(smg);
    const int KC = K >> 5;

    float acc[2][NFR][4];
#pragma unroll
    for (int mi = 0; mi < 2; mi++)
#pragma unroll
        for (int ni = 0; ni < NFR; ni++)
#pragma unroll
            for (int j = 0; j < 4; j++) acc[mi][ni][j] = 0.f;

    auto load_chunk = [&](int i, int buf) {
        const int kt = i << 5;
        const uint32_t db = sb + buf * BUFSZ;
#pragma unroll
        for (int j = 0; j < 2; j++) {
            int e = tid + j * 256;
            int r = e >> 2, s = e & 3;
            size_t g = (size_t)(m_blk + r) * 2048 + kt + s * 8;
            cp16(db + r * ROWB + s * 16, Ahi + g);
            cp16(db + ABUF + r * ROWB + s * 16, Alo + g);
        }
#pragma unroll
        for (int j = 0; j < 2; j++) {
            int e = tid + j * 256;
            int r = e >> 2, s = e & 3;
            cp16(db + 2 * ABUF + r * ROWB + s * 16,
                 Bw + (size_t)(n_blk + r) * K + kt + s * 8);
        }
        CP_COMMIT();
    };

    load_chunk(0, 0);

    const uint32_t aoff = (uint32_t)((warp_m + (lane & 15)) * ROWB + ((lane >> 4) << 4));
    const uint32_t boff = (uint32_t)((warp_n + (lane & 7) + ((lane >> 4) << 3)) * ROWB +
                                     (((lane >> 3) & 1) << 4));

    for (int i = 0; i < KC; i++) {
        const int buf = i & 1;
        if (i + 1 < KC) load_chunk(i + 1, buf ^ 1);
        else CP_COMMIT();
        CP_WAIT(1);
        __syncthreads();

        const uint32_t db = sb + buf * BUFSZ;
#pragma unroll
        for (int ks = 0; ks < 2; ks++) {
            uint32_t ah[2][4], al[2][4];
#pragma unroll
            for (int mi = 0; mi < 2; mi++) {
                ldm4(ah[mi], db + aoff + mi * 16 * ROWB + ks * 32);
                ldm4(al[mi], db + ABUF + aoff + mi * 16 * ROWB + ks * 32);
            }
            uint32_t b[NFR][2];
#pragma unroll
            for (int nj = 0; nj < NFR / 2; nj++) {
                uint32_t r[4];
                ldm4(r, db + 2 * ABUF + boff + nj * 16 * ROWB + ks * 32);
                b[2*nj][0] = r[0]; b[2*nj][1] = r[1];
                b[2*nj+1][0] = r[2]; b[2*nj+1][1] = r[3];
            }
#pragma unroll
            for (int mi = 0; mi < 2; mi++)
#pragma unroll
                for (int ni = 0; ni < NFR; ni++) {
                    mma16816(acc[mi][ni], ah[mi], b[ni]);
                    mma16816(acc[mi][ni], al[mi], b[ni]);
                }
        }
        __syncthreads();
    }

    const int g = lane >> 2, c2 = (lane & 3) * 2;
#pragma unroll
    for (int mi = 0; mi < 2; mi++) {
#pragma unroll
        for (int ni = 0; ni < NFR; ni++) {
            int col = n_blk + warp_n + ni * 8 + c2;
#pragma unroll
            for (int hrow = 0; hrow < 2; hrow++) {
                int m = m_blk + warp_m + mi * 16 + g + hrow * 8;
                float v0 = acc[mi][ni][hrow * 2];
                float v1 = acc[mi][ni][hrow * 2 + 1];
                if (col < 1536)
                    *(uint32_t*)(Chi + (size_t)m * 1536 + col) = packh2(v0, v1);
                else if (col < 1600)
                    *(uint32_t*)(C1 + (size_t)m * 64 + col - 1536) = packh2(v0, v1);
            }
        }
    }
}

// ---------------------------------------------------------------------------
// Fused q + kv projections (1-term, BN=64, k=64 chunks, ROWB=144, 2 stages,
// occupancy 2). grid (7, 32, 16): x<3 -> q slice, x>=3 -> kv slice.
// ---------------------------------------------------------------------------
#define QROWB 144
#define QABUF (128 * QROWB)     // 18432
#define QBBUF (64 * QROWB)      // 9216
#define QBUFSZ (QABUF + QBBUF)  // 27648
#define QKV_SMEM (2 * QBUFSZ)   // 55296

__global__ __launch_bounds__(256, 2)
void qkv_gemm(const __half* __restrict__ cc, const __half* __restrict__ WqT,
              const __half* __restrict__ WkvT,
              __half* __restrict__ qh, __half* __restrict__ kc,
              __half* __restrict__ vs)
{
    extern __shared__ __align__(16) char smg[];

    const int xb = blockIdx.x;
    const bool isq = xb < 3;
    const int tid  = threadIdx.x;
    const int wid  = tid >> 5;
    const int lane = tid & 31;
    const int m_blk = blockIdx.y * 128;
    const int head  = blockIdx.z;
    const int warp_m = (wid >> 1) * 32;
    const int warp_n = (wid & 1) * 32;

    const __half* Ap;
    const __half* Bp;
    int K, n_blk;
    if (isq) {
        Ap = cc + 512; K = 1024; n_blk = xb * 64;
        Bp = WqT + (size_t)head * 192 * 1024 + (size_t)n_blk * 1024;
    } else {
        Ap = cc; K = 512; n_blk = (xb - 3) * 64;
        Bp = WkvT + (size_t)head * 256 * 512 + (size_t)n_blk * 512;
    }

    const uint32_t sb = smem_u32(smg);
    const int KC = K >> 6;

    float acc[2][4][4];
#pragma unroll
    for (int mi = 0; mi < 2; mi++)
#pragma unroll
        for (int ni = 0; ni < 4; ni++)
#pragma unroll
            for (int j = 0; j < 4; j++) acc[mi][ni][j] = 0.f;

    auto load_chunk = [&](int i, int buf) {
        const int kt = i << 6;
        const uint32_t db = sb + buf * QBUFSZ;
#pragma unroll
        for (int j = 0; j < 4; j++) {
            int e = tid + j * 256;          // 0..1023: 128 rows x 8 segs
            int r = e >> 3, s = e & 7;
            cp16(db + r * QROWB + s * 16, Ap + (size_t)(m_blk + r) * 1536 + kt + s * 8);
        }
#pragma unroll
        for (int j = 0; j < 2; j++) {
            int e = tid + j * 256;          // 0..511: 64 rows x 8 segs
            int r = e >> 3, s = e & 7;
            cp16(db + QABUF + r * QROWB + s * 16, Bp + (size_t)r * K + kt + s * 8);
        }
        CP_COMMIT();
    };

    load_chunk(0, 0);

    const uint32_t aoff = (uint32_t)((warp_m + (lane & 15)) * QROWB + ((lane >> 4) << 4));
    const uint32_t boff = (uint32_t)((warp_n + (lane & 7) + ((lane >> 4) << 3)) * QROWB +
                                     (((lane >> 3) & 1) << 4));

    for (int i = 0; i < KC; i++) {
        const int buf = i & 1;
        if (i + 1 < KC) load_chunk(i + 1, buf ^ 1);
        else CP_COMMIT();
        CP_WAIT(1);
        __syncthreads();

        const uint32_t db = sb + buf * QBUFSZ;
#pragma unroll
        for (int ks = 0; ks < 4; ks++) {
            uint32_t a[2][4];
#pragma unroll
            for (int mi = 0; mi < 2; mi++)
                ldm4(a[mi], db + aoff + mi * 16 * QROWB + ks * 32);
            uint32_t b[4][2];
#pragma unroll
            for (int nj = 0; nj < 2; nj++) {
                uint32_t r[4];
                ldm4(r, db + QABUF + boff + nj * 16 * QROWB + ks * 32);
                b[2*nj][0] = r[0]; b[2*nj][1] = r[1];
                b[2*nj+1][0] = r[2]; b[2*nj+1][1] = r[3];
            }
#pragma unroll
            for (int mi = 0; mi < 2; mi++)
#pragma unroll
                for (int ni = 0; ni < 4; ni++)
                    mma16816(acc[mi][ni], a[mi], b[ni]);
        }
        __syncthreads();
    }

    const int g = lane >> 2, c2 = (lane & 3) * 2;
#pragma unroll
    for (int mi = 0; mi < 2; mi++) {
#pragma unroll
        for (int ni = 0; ni < 4; ni++) {
            int col = n_blk + warp_n + ni * 8 + c2;
#pragma unroll
            for (int hrow = 0; hrow < 2; hrow++) {
                int m = m_blk + warp_m + mi * 16 + g + hrow * 8;
                float v0 = acc[mi][ni][hrow * 2];
                float v1 = acc[mi][ni][hrow * 2 + 1];
                int b = m >> 11, s = m & 2047;
                size_t rowb = (size_t)((b * Hq + head) * Sq + s);
                if (isq) {
                    *(uint32_t*)(qh + rowb * DQK + col) = packh2(v0, v1);
                } else if (col < 128) {
                    *(uint32_t*)(kc + rowb * 128 + col) = packh2(v0, v1);
                } else {
                    *(uint32_t*)(vs + rowb * 128 + col - 128) = packh2(v0, v1);
                }
            }
        }
    }
}

// ---------------------------------------------------------------------------
// Causal flash attention, fp16 operands, fp32 accum.
// K tile assembled in the loader from per-head k_c (cols 0-127) and the
// head-shared kr buffer (cols 128-191). grid (S/128, B*H), 256 threads.
// ---------------------------------------------------------------------------
#define QSTRB 400   // 192 fp16 = 384 B + 16 pad
#define VSTRB 272   // 128 fp16 = 256 B + 16 pad
#define KBUF0 51200          // 2 x 25600 (K assembled)
#define VBUF0 102400         // 2 x 17408 (V)
#define ATTN_SMEM 137216

__global__ __launch_bounds__(256, 1)
void attn_mma(const __half* __restrict__ q_,
              const __half* __restrict__ kc_, const __half* __restrict__ kr_,
              const __half* __restrict__ v_, float* __restrict__ O)
{
    extern __shared__ __align__(16) char sm[];
    const uint32_t sb = smem_u32(sm);

    const int bh = blockIdx.y;
    const int b = bh >> 4, h = bh & 15;
    const int s0 = ((int)gridDim.x - 1 - (int)blockIdx.x) * 128;
    const int tid = threadIdx.x, wid = tid >> 5, lane = tid & 31;
    const int warp_m = wid * 16;
    const int g = lane >> 2, c2 = (lane & 3) * 2;

    const size_t qb  = (size_t)bh * Sq * DQK;
    const size_t kcb = (size_t)bh * Sq * DKq;
    const size_t krb = (size_t)b * Sq * DRq;
    const size_t vb  = (size_t)bh * Sq * DVq;

    const uint32_t a_off = (uint32_t)((warp_m + (lane & 15)) * QSTRB + ((lane >> 4) << 4));
    const uint32_t b_off = (uint32_t)(((lane & 7) + ((lane >> 4) << 3)) * QSTRB +
                                      (((lane >> 3) & 1) << 4));
    const uint32_t v_off = (uint32_t)((lane & 15) * VSTRB + ((lane >> 4) << 4));

    // ---- stage Q (resident) ----
    {
        const __half* sh = q_ + qb + (size_t)s0 * DQK;
#pragma unroll
        for (int j = 0; j < 12; j++) {
            int e = tid + j * 256;            // 0..3071
            int r = e / 24, s = e - r * 24;
            cp16(sb + r * QSTRB + s * 16, sh + r * 192 + s * 8);
        }
        CP_COMMIT();
    }

    // ---- K/V tile loader: K = [k_c | kr] ----
    auto load_kv = [&](int jb, int buf) {
        const uint32_t kb = sb + KBUF0 + buf * 25600;
        const uint32_t vbuf = sb + VBUF0 + buf * 17408;
        const __half* skc = kc_ + kcb + (size_t)(jb * 64) * DKq;
        const __half* skr = kr_ + krb + (size_t)(jb * 64) * DRq;
        const __half* sv  = v_ + vb + (size_t)(jb * 64) * DVq;
#pragma unroll
        for (int j = 0; j < 6; j++) {
            int e = tid + j * 256;            // 0..1535 = 64 rows x 24 segs
            int r = e / 24, s = e - r * 24;
            if (s < 16)
                cp16(kb + r * QSTRB + s * 16, skc + r * 128 + s * 8);
            else
                cp16(kb + r * QSTRB + s * 16, skr + r * 64 + (s - 16) * 8);
        }
#pragma unroll
        for (int j = 0; j < 4; j++) {
            int e = tid + j * 256;            // 0..1023
            int r = e >> 4, s = e & 15;
            cp16(vbuf + r * VSTRB + s * 16, sv + r * 128 + s * 8);
        }
        CP_COMMIT();
    };

    const int jmax = (s0 >> 6) + 1;
    load_kv(0, 0);

    float accO[16][4];
#pragma unroll
    for (int nf = 0; nf < 16; nf++)
#pragma unroll
        for (int j = 0; j < 4; j++) accO[nf][j] = 0.f;
    float m0 = -INFINITY, m1 = -INFINITY, l0 = 0.f, l1 = 0.f;

    const float scale = 0.07216878364870322f;   // 1/sqrt(192)
    const int row0 = s0 + warp_m + g;
    const int row1 = row0 + 8;

    for (int jb = 0; jb <= jmax; jb++) {
        const int buf = jb & 1;
        if (jb < jmax) {
            load_kv(jb + 1, buf ^ 1);
            CP_WAIT(1);
        } else {
            CP_WAIT(0);
        }
        __syncthreads();

        const uint32_t kb = sb + KBUF0 + buf * 25600;
        const uint32_t vbuf = sb + VBUF0 + buf * 17408;

        // ---- S = Q K^T ----
        float S[8][4];
#pragma unroll
        for (int nf = 0; nf < 8; nf++)
#pragma unroll
            for (int j = 0; j < 4; j++) S[nf][j] = 0.f;

#pragma unroll
        for (int ks = 0; ks < 12; ks++) {
            uint32_t ah[4];
            ldm4(ah, sb + a_off + ks * 32);
#pragma unroll
            for (int p = 0; p < 4; p++) {
                uint32_t bv[4];
                ldm4(bv, kb + b_off + p * 16 * QSTRB + ks * 32);
                mma16816(S[2*p],   ah, bv);
                mma16816(S[2*p+1], ah, bv + 2);
            }
        }

        // ---- scale + causal mask ----
        const bool domask = ((jb << 6) + 63) > row0;
#pragma unroll
        for (int nf = 0; nf < 8; nf++) {
#pragma unroll
            for (int j = 0; j < 4; j++) S[nf][j] *= scale;
            if (domask) {
                int key0 = (jb << 6) + nf * 8 + c2;
                if (key0     > row0) S[nf][0] = -INFINITY;
                if (key0 + 1 > row0) S[nf][1] = -INFINITY;
                if (key0     > row1) S[nf][2] = -INFINITY;
                if (key0 + 1 > row1) S[nf][3] = -INFINITY;
            }
        }

        // ---- online softmax ----
        float rm0 = -INFINITY, rm1 = -INFINITY;
#pragma unroll
        for (int nf = 0; nf < 8; nf++) {
            rm0 = fmaxf(rm0, fmaxf(S[nf][0], S[nf][1]));
            rm1 = fmaxf(rm1, fmaxf(S[nf][2], S[nf][3]));
        }
        rm0 = fmaxf(rm0, __shfl_xor_sync(0xffffffffu, rm0, 1));
        rm0 = fmaxf(rm0, __shfl_xor_sync(0xffffffffu, rm0, 2));
        rm1 = fmaxf(rm1, __shfl_xor_sync(0xffffffffu, rm1, 1));
        rm1 = fmaxf(rm1, __shfl_xor_sync(0xffffffffu, rm1, 2));

        float mn0 = fmaxf(m0, rm0), mn1 = fmaxf(m1, rm1);
        float al0 = __expf(m0 - mn0), al1 = __expf(m1 - mn1);
        m0 = mn0; m1 = mn1;

        float rs0 = 0.f, rs1 = 0.f;
#pragma unroll
        for (int nf = 0; nf < 8; nf++) {
            S[nf][0] = __expf(S[nf][0] - mn0);
            S[nf][1] = __expf(S[nf][1] - mn0);
            S[nf][2] = __expf(S[nf][2] - mn1);
            S[nf][3] = __expf(S[nf][3] - mn1);
            rs0 += S[nf][0] + S[nf][1];
            rs1 += S[nf][2] + S[nf][3];
        }
        rs0 += __shfl_xor_sync(0xffffffffu, rs0, 1);
        rs0 += __shfl_xor_sync(0xffffffffu, rs0, 2);
        rs1 += __shfl_xor_sync(0xffffffffu, rs1, 1);
        rs1 += __shfl_xor_sync(0xffffffffu, rs1, 2);
        l0 = l0 * al0 + rs0;
        l1 = l1 * al1 + rs1;

#pragma unroll
        for (int nf = 0; nf < 16; nf++) {
            accO[nf][0] *= al0; accO[nf][1] *= al0;
            accO[nf][2] *= al1; accO[nf][3] *= al1;
        }

        // ---- pack P fragments (single fp16) ----
        uint32_t ph[4][4];
#pragma unroll
        for (int t = 0; t < 4; t++) {
            ph[t][0] = packh2(S[2*t][0],   S[2*t][1]);
            ph[t][1] = packh2(S[2*t][2],   S[2*t][3]);
            ph[t][2] = packh2(S[2*t+1][0], S[2*t+1][1]);
            ph[t][3] = packh2(S[2*t+1][2], S[2*t+1][3]);
        }

        // ---- O += P V ----
#pragma unroll
        for (int t = 0; t < 4; t++) {
#pragma unroll
            for (int p = 0; p < 8; p++) {
                uint32_t bv[4];
                ldm4t(bv, vbuf + v_off + t * 16 * VSTRB + p * 32);
                mma16816(accO[2*p],   ph[t], bv);
                mma16816(accO[2*p+1], ph[t], bv + 2);
            }
        }
        __syncthreads();
    }

    // ---- epilogue ----
    float inv0 = 1.0f / l0, inv1 = 1.0f / l1;
#pragma unroll
    for (int nf = 0; nf < 16; nf++) {
        int col = h * DVq + nf * 8 + c2;
        size_t o0 = ((size_t)(b * Sq + row0)) * (size_t)(Hq * DVq) + col;
        size_t o1 = ((size_t)(b * Sq + row1)) * (size_t)(Hq * DVq) + col;
        *(float2*)(O + o0) = make_float2(accO[nf][0] * inv0, accO[nf][1] * inv0);
        *(float2*)(O + o1) = make_float2(accO[nf][2] * inv1, accO[nf][3] * inv1);
    }
}

// ---------------------------------------------------------------------------
extern "C" void kernel_launch(void* const* d_in, const int* in_sizes, int n_in,
                              void* d_out, int out_size)
{
    (void)in_sizes; (void)n_in; (void)out_size;
    const float* x    = (const float*)d_in[0];
    const float* W_c  = (const float*)d_in[1];
    const float* W_cp = (const float*)d_in[2];
    const float* W_qc = (const float*)d_in[3];
    const float* W_qr = (const float*)d_in[4];
    const float* W_kc = (const float*)d_in[5];
    const float* W_kr = (const float*)d_in[6];
    const float* W_v  = (const float*)d_in[7];
    float* out = (float*)d_out;

    char* arena;
    cudaGetSymbolAddress((void**)&arena, g_arena);
    __half* xhi   = (__half*)(arena + O_XHI);
    __half* xlo   = (__half*)(arena + O_XLO);
    __half* WxT   = (__half*)(arena + O_WXT);
    __half* WqT   = (__half*)(arena + O_WQT);
    __half* WkvT  = (__half*)(arena + O_WKVT);
    __half* cc    = (__half*)(arena + O_CC);
    __half* qh    = (__half*)(arena + O_QH);
    __half* kc    = (__half*)(arena + O_KC);
    __half* vs    = (__half*)(arena + O_VS);
    __half* kr    = (__half*)(arena + O_KR);

    const int GSM_CC = 2 * (2 * 10240 + 128 * 80);  // 61440
    cudaFuncSetAttribute(cc_gemm, cudaFuncAttributeMaxDynamicSharedMemorySize, GSM_CC);
    cudaFuncSetAttribute(qkv_gemm, cudaFuncAttributeMaxDynamicSharedMemorySize, QKV_SMEM);
    cudaFuncSetAttribute(attn_mma, cudaFuncAttributeMaxDynamicSharedMemorySize, ATTN_SMEM);

    // prep: x split + all weight transposes in one kernel
    split_f32<<<32768, 256>>>(x, xhi, xlo);
    tround_all<<<8320, 256>>>(W_c, W_cp, W_qc, W_qr, W_kc, W_v, W_kr,
                              WxT, WqT, WkvT);

    // fused c+cp+kr projection (2-term from x), cc stored single fp16
    cc_gemm<<<dim3(13, 32, 1), 256, GSM_CC>>>(xhi, xlo, WxT, kr, cc, 2048);

    // fused q + kv projections (1-term from cc), k=64 chunks, occ 2
    qkv_gemm<<<dim3(7, 32, 16), 256, QKV_SMEM>>>(cc, WqT, WkvT, qh, kc, vs);

    attn_mma<<<dim3(Sq / 128, Bq * Hq), 256, ATTN_SMEM>>>(qh, kc, kr, vs, out);
}

// round 15
// speedup vs baseline: 1.1080x; 1.0640x over previous
#include <cuda_runtime.h>
#include <cuda_fp16.h>
#include <math.h>
#include <stdint.h>

// Problem constants
#define Bq   2
#define Sq   2048
#define DIMq 2048
#define Hq   16
#define DKq  128
#define DRq  64
#define DCq  512
#define DCPq 1024
#define DVq  128
#define DQK  192
#define Mrows (Bq*Sq)      // 4096

// ------------------------- scratch arena (bss) ------------------------------
#define O_XHI    0ULL
#define O_XLO    16777216ULL
#define O_WXT    33554432ULL      // packed [1664][2048]: c[0,512) cp[512,1536) kr[1536,1600) pad
#define O_WQT    40370176ULL      // packed [16][192][1024] = flat [3072][1024]
#define O_WKVT   46661632ULL      // packed [16][256][512]  = flat [4096][512]
#define O_CC     50855936ULL      // cc single fp16 [4096][1536]
#define O_QH     63438848ULL      // q single [B,H,S,192]
#define O_KC     88604672ULL      // k_c single [B,H,S,128]
#define O_VS     105381888ULL     // v single [B,H,S,128]
#define O_KR     122159104ULL     // kr single [B,S,64] (shared across heads)
#define ARENA_BYTES 122683392ULL

__device__ __align__(256) char g_arena[ARENA_BYTES];

// ------------------------- helpers ------------------------------------------
__device__ __forceinline__ uint32_t smem_u32(const void* p) {
    uint32_t a;
    asm("{ .reg .u64 t; cvta.to.shared.u64 t, %1; cvt.u32.u64 %0, t; }" : "=r"(a) : "l"(p));
    return a;
}

__device__ __forceinline__ void cp16(uint32_t dst, const void* src) {
    asm volatile("cp.async.cg.shared.global [%0], [%1], 16;" :: "r"(dst), "l"(src));
}
#define CP_COMMIT() asm volatile("cp.async.commit_group;" ::: "memory")
#define CP_WAIT(n)  asm volatile("cp.async.wait_group %0;" :: "n"(n) : "memory")

__device__ __forceinline__ void ldm4(uint32_t* r, uint32_t addr) {
    asm volatile("ldmatrix.sync.aligned.m8n8.x4.shared.b16 {%0,%1,%2,%3}, [%4];"
                 : "=r"(r[0]), "=r"(r[1]), "=r"(r[2]), "=r"(r[3]) : "r"(addr));
}
__device__ __forceinline__ void ldm4t(uint32_t* r, uint32_t addr) {
    asm volatile("ldmatrix.sync.aligned.m8n8.x4.trans.shared.b16 {%0,%1,%2,%3}, [%4];"
                 : "=r"(r[0]), "=r"(r[1]), "=r"(r[2]), "=r"(r[3]) : "r"(addr));
}

__device__ __forceinline__ void mma16816(float* d, const uint32_t* a, const uint32_t* b) {
    asm volatile("mma.sync.aligned.m16n8k16.row.col.f32.f16.f16.f32 "
                 "{%0,%1,%2,%3}, {%4,%5,%6,%7}, {%8,%9}, {%0,%1,%2,%3};"
                 : "+f"(d[0]), "+f"(d[1]), "+f"(d[2]), "+f"(d[3])
                 : "r"(a[0]), "r"(a[1]), "r"(a[2]), "r"(a[3]), "r"(b[0]), "r"(b[1]));
}

__device__ __forceinline__ uint32_t packh2(float x, float y) {
    __half2 t = __floats2half2_rn(x, y);
    return *(uint32_t*)&t;
}

// ---------------------------------------------------------------------------
// split x fp32 -> fp16 hi/lo
// ---------------------------------------------------------------------------
__global__ __launch_bounds__(256)
void split_f32(const float* __restrict__ A, __half* __restrict__ hi,
               __half* __restrict__ lo)
{
    int i = blockIdx.x * 256 + threadIdx.x;
    float v = A[i];
    __half h = __float2half_rn(v);
    hi[i] = h;
    lo[i] = __float2half_rn(v - __half2float(h));
}

// ---------------------------------------------------------------------------
// One kernel for ALL weight transposes+roundings (8320 tiles of 32x32).
// ---------------------------------------------------------------------------
__device__ __forceinline__ void tr_tile(const float* __restrict__ W,
                                        __half* __restrict__ out,
                                        int K, int N, int bx, int by)
{
    __shared__ float t[32][33];
    const int k0 = by * 32, n0 = bx * 32;
    const int x = threadIdx.x & 31, y = threadIdx.x >> 5;
#pragma unroll
    for (int i = 0; i < 4; i++)
        t[y + 8*i][x] = W[(size_t)(k0 + y + 8*i) * N + n0 + x];
    __syncthreads();
#pragma unroll
    for (int i = 0; i < 4; i++)
        out[(size_t)(n0 + y + 8*i) * K + k0 + x] = __float2half_rn(t[x][y + 8*i]);
}

__global__ __launch_bounds__(256)
void tround_all(const float* __restrict__ W_c, const float* __restrict__ W_cp,
                const float* __restrict__ W_qc, const float* __restrict__ W_qr,
                const float* __restrict__ W_kc, const float* __restrict__ W_v,
                const float* __restrict__ W_kr,
                __half* __restrict__ WxT, __half* __restrict__ WqT,
                __half* __restrict__ WkvT)
{
    const int bid = blockIdx.x;
    if (bid < 1024) {                       // W_c -> WxT rows [0,512)
        tr_tile(W_c, WxT, 2048, 512, bid & 15, bid >> 4);
    } else if (bid < 3072) {                // W_cp -> WxT rows [512,1536)
        int l = bid - 1024;
        tr_tile(W_cp, WxT + (size_t)512 * 2048, 2048, 1024, l & 31, l >> 5);
    } else if (bid < 5120) {                // W_qc
        int l = bid - 3072;
        int h = l >> 7, rem = l & 127;
        tr_tile(W_qc + (size_t)h * 1024 * 128, WqT + (size_t)h * 192 * 1024,
                1024, 128, rem & 3, rem >> 2);
    } else if (bid < 6144) {                // W_qr
        int l = bid - 5120;
        int h = l >> 6, rem = l & 63;
        tr_tile(W_qr + (size_t)h * 1024 * 64, WqT + (size_t)h * 192 * 1024 + 128 * 1024,
                1024, 64, rem & 1, rem >> 1);
    } else if (bid < 7168) {                // W_kc
        int l = bid - 6144;
        int h = l >> 6, rem = l & 63;
        tr_tile(W_kc + (size_t)h * 512 * 128, WkvT + (size_t)h * 256 * 512,
                512, 128, rem & 3, rem >> 2);
    } else if (bid < 8192) {                // W_v
        int l = bid - 7168;
        int h = l >> 6, rem = l & 63;
        tr_tile(W_v + (size_t)h * 512 * 128, WkvT + (size_t)h * 256 * 512 + 128 * 512,
                512, 128, rem & 3, rem >> 2);
    } else {                                // W_kr -> WxT rows [1536,1600)
        int l = bid - 8192;
        tr_tile(W_kr, WxT + (size_t)1536 * 2048, 2048, 64, l & 1, l >> 1);
    }
}

// ---------------------------------------------------------------------------
// cc GEMM (TERMS=2): C = (Ahi+Alo) * W16. k=32 chunks, ROWB=80, 2 stages,
// occupancy 2. col<1536 -> Chi [M][1536]; 1536..1600 -> C1 [M][64].
// ---------------------------------------------------------------------------
__global__ __launch_bounds__(256, 2)
void cc_gemm(const __half* __restrict__ Ahi, const __half* __restrict__ Alo,
             const __half* __restrict__ Bw,
             __half* __restrict__ C1, __half* __restrict__ Chi, int K)
{
    constexpr int ROWB = 80;
    constexpr int ABUF = 128 * ROWB;    // 10240
    constexpr int BBUF = 128 * ROWB;
    constexpr int BUFSZ = 2 * ABUF + BBUF;
    constexpr int NFR  = 8;             // 64 cols per warp

    extern __shared__ __align__(16) char smg[];

    const int tid  = threadIdx.x;
    const int wid  = tid >> 5;
    const int lane = tid & 31;
    const int m_blk = blockIdx.y * 128;
    const int n_blk = blockIdx.x * 128;
    const int warp_m = (wid >> 1) * 32;
    const int warp_n = (wid & 1) * 64;

    const uint32_t sb = smem_u32(smg);
    const int KC = K >> 5;

    float acc[2][NFR][4];
#pragma unroll
    for (int mi = 0; mi < 2; mi++)
#pragma unroll
        for (int ni = 0; ni < NFR; ni++)
#pragma unroll
            for (int j = 0; j < 4; j++) acc[mi][ni][j] = 0.f;

    auto load_chunk = [&](int i, int buf) {
        const int kt = i << 5;
        const uint32_t db = sb + buf * BUFSZ;
#pragma unroll
        for (int j = 0; j < 2; j++) {
            int e = tid + j * 256;
            int r = e >> 2, s = e & 3;
            size_t g = (size_t)(m_blk + r) * 2048 + kt + s * 8;
            cp16(db + r * ROWB + s * 16, Ahi + g);
            cp16(db + ABUF + r * ROWB + s * 16, Alo + g);
        }
#pragma unroll
        for (int j = 0; j < 2; j++) {
            int e = tid + j * 256;
            int r = e >> 2, s = e & 3;
            cp16(db + 2 * ABUF + r * ROWB + s * 16,
                 Bw + (size_t)(n_blk + r) * K + kt + s * 8);
        }
        CP_COMMIT();
    };

    load_chunk(0, 0);

    const uint32_t aoff = (uint32_t)((warp_m + (lane & 15)) * ROWB + ((lane >> 4) << 4));
    const uint32_t boff = (uint32_t)((warp_n + (lane & 7) + ((lane >> 4) << 3)) * ROWB +
                                     (((lane >> 3) & 1) << 4));

    for (int i = 0; i < KC; i++) {
        const int buf = i & 1;
        if (i + 1 < KC) load_chunk(i + 1, buf ^ 1);
        else CP_COMMIT();
        CP_WAIT(1);
        __syncthreads();

        const uint32_t db = sb + buf * BUFSZ;
#pragma unroll
        for (int ks = 0; ks < 2; ks++) {
            uint32_t ah[2][4], al[2][4];
#pragma unroll
            for (int mi = 0; mi < 2; mi++) {
                ldm4(ah[mi], db + aoff + mi * 16 * ROWB + ks * 32);
                ldm4(al[mi], db + ABUF + aoff + mi * 16 * ROWB + ks * 32);
            }
            uint32_t b[NFR][2];
#pragma unroll
            for (int nj = 0; nj < NFR / 2; nj++) {
                uint32_t r[4];
                ldm4(r, db + 2 * ABUF + boff + nj * 16 * ROWB + ks * 32);
                b[2*nj][0] = r[0]; b[2*nj][1] = r[1];
                b[2*nj+1][0] = r[2]; b[2*nj+1][1] = r[3];
            }
#pragma unroll
            for (int mi = 0; mi < 2; mi++)
#pragma unroll
                for (int ni = 0; ni < NFR; ni++) {
                    mma16816(acc[mi][ni], ah[mi], b[ni]);
                    mma16816(acc[mi][ni], al[mi], b[ni]);
                }
        }
        __syncthreads();
    }

    const int g = lane >> 2, c2 = (lane & 3) * 2;
#pragma unroll
    for (int mi = 0; mi < 2; mi++) {
#pragma unroll
        for (int ni = 0; ni < NFR; ni++) {
            int col = n_blk + warp_n + ni * 8 + c2;
#pragma unroll
            for (int hrow = 0; hrow < 2; hrow++) {
                int m = m_blk + warp_m + mi * 16 + g + hrow * 8;
                float v0 = acc[mi][ni][hrow * 2];
                float v1 = acc[mi][ni][hrow * 2 + 1];
                if (col < 1536)
                    *(uint32_t*)(Chi + (size_t)m * 1536 + col) = packh2(v0, v1);
                else if (col < 1600)
                    *(uint32_t*)(C1 + (size_t)m * 64 + col - 1536) = packh2(v0, v1);
            }
        }
    }
}

// ---------------------------------------------------------------------------
// Fused q + kv projections, flat-N view (1-term, 128x128 CTA tile, warp tile
// 32x64, k=64 chunks, ROWB=144, 2 stages, occupancy 2).
// q : [4096,1024] x WqT-flat  [3072][1024] -> cols decode head=col/192
// kv: [4096, 512] x WkvT-flat [4096][ 512] -> cols decode head=col>>8
// grid (56, 32): x<24 -> q n-tile x*128; else kv n-tile (x-24)*128.
// ---------------------------------------------------------------------------
#define QROWB 144
#define QABUF (128 * QROWB)       // 18432
#define QBUFSZ (2 * QABUF)        // 36864 (A + B)
#define QKV_SMEM (2 * QBUFSZ)     // 73728

__global__ __launch_bounds__(256, 2)
void qkv_gemm(const __half* __restrict__ cc, const __half* __restrict__ WqT,
              const __half* __restrict__ WkvT,
              __half* __restrict__ qh, __half* __restrict__ kc,
              __half* __restrict__ vs)
{
    extern __shared__ __align__(16) char smg[];

    const int xb = blockIdx.x;
    const bool isq = xb < 24;
    const int tid  = threadIdx.x;
    const int wid  = tid >> 5;
    const int lane = tid & 31;
    const int m_blk = blockIdx.y * 128;
    const int warp_m = (wid >> 1) * 32;
    const int warp_n = (wid & 1) * 64;

    const __half* Ap;
    const __half* Bp;
    int K, n_blk;
    if (isq) {
        Ap = cc + 512; K = 1024; n_blk = xb * 128;
        Bp = WqT + (size_t)n_blk * 1024;
    } else {
        Ap = cc; K = 512; n_blk = (xb - 24) * 128;
        Bp = WkvT + (size_t)n_blk * 512;
    }

    const uint32_t sb = smem_u32(smg);
    const int KC = K >> 6;

    float acc[2][8][4];
#pragma unroll
    for (int mi = 0; mi < 2; mi++)
#pragma unroll
        for (int ni = 0; ni < 8; ni++)
#pragma unroll
            for (int j = 0; j < 4; j++) acc[mi][ni][j] = 0.f;

    auto load_chunk = [&](int i, int buf) {
        const int kt = i << 6;
        const uint32_t db = sb + buf * QBUFSZ;
#pragma unroll
        for (int j = 0; j < 4; j++) {
            int e = tid + j * 256;          // 0..1023: 128 rows x 8 segs (A)
            int r = e >> 3, s = e & 7;
            cp16(db + r * QROWB + s * 16, Ap + (size_t)(m_blk + r) * 1536 + kt + s * 8);
        }
#pragma unroll
        for (int j = 0; j < 4; j++) {
            int e = tid + j * 256;          // 0..1023: 128 rows x 8 segs (B)
            int r = e >> 3, s = e & 7;
            cp16(db + QABUF + r * QROWB + s * 16, Bp + (size_t)r * K + kt + s * 8);
        }
        CP_COMMIT();
    };

    load_chunk(0, 0);

    const uint32_t aoff = (uint32_t)((warp_m + (lane & 15)) * QROWB + ((lane >> 4) << 4));
    const uint32_t boff = (uint32_t)((warp_n + (lane & 7) + ((lane >> 4) << 3)) * QROWB +
                                     (((lane >> 3) & 1) << 4));

    for (int i = 0; i < KC; i++) {
        const int buf = i & 1;
        if (i + 1 < KC) load_chunk(i + 1, buf ^ 1);
        else CP_COMMIT();
        CP_WAIT(1);
        __syncthreads();

        const uint32_t db = sb + buf * QBUFSZ;
#pragma unroll
        for (int ks = 0; ks < 4; ks++) {
            uint32_t a[2][4];
#pragma unroll
            for (int mi = 0; mi < 2; mi++)
                ldm4(a[mi], db + aoff + mi * 16 * QROWB + ks * 32);
            uint32_t b[8][2];
#pragma unroll
            for (int nj = 0; nj < 4; nj++) {
                uint32_t r[4];
                ldm4(r, db + QABUF + boff + nj * 16 * QROWB + ks * 32);
                b[2*nj][0] = r[0]; b[2*nj][1] = r[1];
                b[2*nj+1][0] = r[2]; b[2*nj+1][1] = r[3];
            }
#pragma unroll
            for (int mi = 0; mi < 2; mi++)
#pragma unroll
                for (int ni = 0; ni < 8; ni++)
                    mma16816(acc[mi][ni], a[mi], b[ni]);
        }
        __syncthreads();
    }

    const int g = lane >> 2, c2 = (lane & 3) * 2;
#pragma unroll
    for (int mi = 0; mi < 2; mi++) {
#pragma unroll
        for (int ni = 0; ni < 8; ni++) {
            int col = n_blk + warp_n + ni * 8 + c2;
#pragma unroll
            for (int hrow = 0; hrow < 2; hrow++) {
                int m = m_blk + warp_m + mi * 16 + g + hrow * 8;
                float v0 = acc[mi][ni][hrow * 2];
                float v1 = acc[mi][ni][hrow * 2 + 1];
                int b = m >> 11, s = m & 2047;
                if (isq) {
                    int head = col / 192, cin = col - head * 192;
                    size_t rowb = (size_t)((b * Hq + head) * Sq + s);
                    *(uint32_t*)(qh + rowb * DQK + cin) = packh2(v0, v1);
                } else {
                    int head = col >> 8, cin = col & 255;
                    size_t rowb = (size_t)((b * Hq + head) * Sq + s);
                    if (cin < 128)
                        *(uint32_t*)(kc + rowb * 128 + cin) = packh2(v0, v1);
                    else
                        *(uint32_t*)(vs + rowb * 128 + cin - 128) = packh2(v0, v1);
                }
            }
        }
    }
}

// ---------------------------------------------------------------------------
// Causal flash attention, fp16 operands, fp32 accum.
// K tile assembled in the loader from per-head k_c (cols 0-127) and the
// head-shared kr buffer (cols 128-191). grid (S/128, B*H), 256 threads.
// ---------------------------------------------------------------------------
#define QSTRB 400   // 192 fp16 = 384 B + 16 pad
#define VSTRB 272   // 128 fp16 = 256 B + 16 pad
#define KBUF0 51200          // 2 x 25600 (K assembled)
#define VBUF0 102400         // 2 x 17408 (V)
#define ATTN_SMEM 137216

__global__ __launch_bounds__(256, 1)
void attn_mma(const __half* __restrict__ q_,
              const __half* __restrict__ kc_, const __half* __restrict__ kr_,
              const __half* __restrict__ v_, float* __restrict__ O)
{
    extern __shared__ __align__(16) char sm[];
    const uint32_t sb = smem_u32(sm);

    const int bh = blockIdx.y;
    const int b = bh >> 4, h = bh & 15;
    const int s0 = ((int)gridDim.x - 1 - (int)blockIdx.x) * 128;
    const int tid = threadIdx.x, wid = tid >> 5, lane = tid & 31;
    const int warp_m = wid * 16;
    const int g = lane >> 2, c2 = (lane & 3) * 2;

    const size_t qb  = (size_t)bh * Sq * DQK;
    const size_t kcb = (size_t)bh * Sq * DKq;
    const size_t krb = (size_t)b * Sq * DRq;
    const size_t vb  = (size_t)bh * Sq * DVq;

    const uint32_t a_off = (uint32_t)((warp_m + (lane & 15)) * QSTRB + ((lane >> 4) << 4));
    const uint32_t b_off = (uint32_t)(((lane & 7) + ((lane >> 4) << 3)) * QSTRB +
                                      (((lane >> 3) & 1) << 4));
    const uint32_t v_off = (uint32_t)((lane & 15) * VSTRB + ((lane >> 4) << 4));

    // ---- stage Q (resident) ----
    {
        const __half* sh = q_ + qb + (size_t)s0 * DQK;
#pragma unroll
        for (int j = 0; j < 12; j++) {
            int e = tid + j * 256;            // 0..3071
            int r = e / 24, s = e - r * 24;
            cp16(sb + r * QSTRB + s * 16, sh + r * 192 + s * 8);
        }
        CP_COMMIT();
    }

    // ---- K/V tile loader: K = [k_c | kr] ----
    auto load_kv = [&](int jb, int buf) {
        const uint32_t kb = sb + KBUF0 + buf * 25600;
        const uint32_t vbuf = sb + VBUF0 + buf * 17408;
        const __half* skc = kc_ + kcb + (size_t)(jb * 64) * DKq;
        const __half* skr = kr_ + krb + (size_t)(jb * 64) * DRq;
        const __half* sv  = v_ + vb + (size_t)(jb * 64) * DVq;
#pragma unroll
        for (int j = 0; j < 6; j++) {
            int e = tid + j * 256;            // 0..1535 = 64 rows x 24 segs
            int r = e / 24, s = e - r * 24;
            if (s < 16)
                cp16(kb + r * QSTRB + s * 16, skc + r * 128 + s * 8);
            else
                cp16(kb + r * QSTRB + s * 16, skr + r * 64 + (s - 16) * 8);
        }
#pragma unroll
        for (int j = 0; j < 4; j++) {
            int e = tid + j * 256;            // 0..1023
            int r = e >> 4, s = e & 15;
            cp16(vbuf + r * VSTRB + s * 16, sv + r * 128 + s * 8);
        }
        CP_COMMIT();
    };

    const int jmax = (s0 >> 6) + 1;
    load_kv(0, 0);

    float accO[16][4];
#pragma unroll
    for (int nf = 0; nf < 16; nf++)
#pragma unroll
        for (int j = 0; j < 4; j++) accO[nf][j] = 0.f;
    float m0 = -INFINITY, m1 = -INFINITY, l0 = 0.f, l1 = 0.f;

    const float scale = 0.07216878364870322f;   // 1/sqrt(192)
    const int row0 = s0 + warp_m + g;
    const int row1 = row0 + 8;

    for (int jb = 0; jb <= jmax; jb++) {
        const int buf = jb & 1;
        if (jb < jmax) {
            load_kv(jb + 1, buf ^ 1);
            CP_WAIT(1);
        } else {
            CP_WAIT(0);
        }
        __syncthreads();

        const uint32_t kb = sb + KBUF0 + buf * 25600;
        const uint32_t vbuf = sb + VBUF0 + buf * 17408;

        // ---- S = Q K^T ----
        float S[8][4];
#pragma unroll
        for (int nf = 0; nf < 8; nf++)
#pragma unroll
            for (int j = 0; j < 4; j++) S[nf][j] = 0.f;

#pragma unroll
        for (int ks = 0; ks < 12; ks++) {
            uint32_t ah[4];
            ldm4(ah, sb + a_off + ks * 32);
#pragma unroll
            for (int p = 0; p < 4; p++) {
                uint32_t bv[4];
                ldm4(bv, kb + b_off + p * 16 * QSTRB + ks * 32);
                mma16816(S[2*p],   ah, bv);
                mma16816(S[2*p+1], ah, bv + 2);
            }
        }

        // ---- scale + causal mask ----
        const bool domask = ((jb << 6) + 63) > row0;
#pragma unroll
        for (int nf = 0; nf < 8; nf++) {
#pragma unroll
            for (int j = 0; j < 4; j++) S[nf][j] *= scale;
            if (domask) {
                int key0 = (jb << 6) + nf * 8 + c2;
                if (key0     > row0) S[nf][0] = -INFINITY;
                if (key0 + 1 > row0) S[nf][1] = -INFINITY;
                if (key0     > row1) S[nf][2] = -INFINITY;
                if (key0 + 1 > row1) S[nf][3] = -INFINITY;
            }
        }

        // ---- online softmax ----
        float rm0 = -INFINITY, rm1 = -INFINITY;
#pragma unroll
        for (int nf = 0; nf < 8; nf++) {
            rm0 = fmaxf(rm0, fmaxf(S[nf][0], S[nf][1]));
            rm1 = fmaxf(rm1, fmaxf(S[nf][2], S[nf][3]));
        }
        rm0 = fmaxf(rm0, __shfl_xor_sync(0xffffffffu, rm0, 1));
        rm0 = fmaxf(rm0, __shfl_xor_sync(0xffffffffu, rm0, 2));
        rm1 = fmaxf(rm1, __shfl_xor_sync(0xffffffffu, rm1, 1));
        rm1 = fmaxf(rm1, __shfl_xor_sync(0xffffffffu, rm1, 2));

        float mn0 = fmaxf(m0, rm0), mn1 = fmaxf(m1, rm1);
        float al0 = __expf(m0 - mn0), al1 = __expf(m1 - mn1);
        m0 = mn0; m1 = mn1;

        float rs0 = 0.f, rs1 = 0.f;
#pragma unroll
        for (int nf = 0; nf < 8; nf++) {
            S[nf][0] = __expf(S[nf][0] - mn0);
            S[nf][1] = __expf(S[nf][1] - mn0);
            S[nf][2] = __expf(S[nf][2] - mn1);
            S[nf][3] = __expf(S[nf][3] - mn1);
            rs0 += S[nf][0] + S[nf][1];
            rs1 += S[nf][2] + S[nf][3];
        }
        rs0 += __shfl_xor_sync(0xffffffffu, rs0, 1);
        rs0 += __shfl_xor_sync(0xffffffffu, rs0, 2);
        rs1 += __shfl_xor_sync(0xffffffffu, rs1, 1);
        rs1 += __shfl_xor_sync(0xffffffffu, rs1, 2);
        l0 = l0 * al0 + rs0;
        l1 = l1 * al1 + rs1;

#pragma unroll
        for (int nf = 0; nf < 16; nf++) {
            accO[nf][0] *= al0; accO[nf][1] *= al0;
            accO[nf][2] *= al1; accO[nf][3] *= al1;
        }

        // ---- pack P fragments (single fp16) ----
        uint32_t ph[4][4];
#pragma unroll
        for (int t = 0; t < 4; t++) {
            ph[t][0] = packh2(S[2*t][0],   S[2*t][1]);
            ph[t][1] = packh2(S[2*t][2],   S[2*t][3]);
            ph[t][2] = packh2(S[2*t+1][0], S[2*t+1][1]);
            ph[t][3] = packh2(S[2*t+1][2], S[2*t+1][3]);
        }

        // ---- O += P V ----
#pragma unroll
        for (int t = 0; t < 4; t++) {
#pragma unroll
            for (int p = 0; p < 8; p++) {
                uint32_t bv[4];
                ldm4t(bv, vbuf + v_off + t * 16 * VSTRB + p * 32);
                mma16816(accO[2*p],   ph[t], bv);
                mma16816(accO[2*p+1], ph[t], bv + 2);
            }
        }
        __syncthreads();
    }

    // ---- epilogue ----
    float inv0 = 1.0f / l0, inv1 = 1.0f / l1;
#pragma unroll
    for (int nf = 0; nf < 16; nf++) {
        int col = h * DVq + nf * 8 + c2;
        size_t o0 = ((size_t)(b * Sq + row0)) * (size_t)(Hq * DVq) + col;
        size_t o1 = ((size_t)(b * Sq + row1)) * (size_t)(Hq * DVq) + col;
        *(float2*)(O + o0) = make_float2(accO[nf][0] * inv0, accO[nf][1] * inv0);
        *(float2*)(O + o1) = make_float2(accO[nf][2] * inv1, accO[nf][3] * inv1);
    }
}

// ---------------------------------------------------------------------------
extern "C" void kernel_launch(void* const* d_in, const int* in_sizes, int n_in,
                              void* d_out, int out_size)
{
    (void)in_sizes; (void)n_in; (void)out_size;
    const float* x    = (const float*)d_in[0];
    const float* W_c  = (const float*)d_in[1];
    const float* W_cp = (const float*)d_in[2];
    const float* W_qc = (const float*)d_in[3];
    const float* W_qr = (const float*)d_in[4];
    const float* W_kc = (const float*)d_in[5];
    const float* W_kr = (const float*)d_in[6];
    const float* W_v  = (const float*)d_in[7];
    float* out = (float*)d_out;

    char* arena;
    cudaGetSymbolAddress((void**)&arena, g_arena);
    __half* xhi   = (__half*)(arena + O_XHI);
    __half* xlo   = (__half*)(arena + O_XLO);
    __half* WxT   = (__half*)(arena + O_WXT);
    __half* WqT   = (__half*)(arena + O_WQT);
    __half* WkvT  = (__half*)(arena + O_WKVT);
    __half* cc    = (__half*)(arena + O_CC);
    __half* qh    = (__half*)(arena + O_QH);
    __half* kc    = (__half*)(arena + O_KC);
    __half* vs    = (__half*)(arena + O_VS);
    __half* kr    = (__half*)(arena + O_KR);

    const int GSM_CC = 2 * (2 * 10240 + 128 * 80);  // 61440
    cudaFuncSetAttribute(cc_gemm, cudaFuncAttributeMaxDynamicSharedMemorySize, GSM_CC);
    cudaFuncSetAttribute(qkv_gemm, cudaFuncAttributeMaxDynamicSharedMemorySize, QKV_SMEM);
    cudaFuncSetAttribute(attn_mma, cudaFuncAttributeMaxDynamicSharedMemorySize, ATTN_SMEM);

    // prep: x split + all weight transposes in one kernel
    split_f32<<<32768, 256>>>(x, xhi, xlo);
    tround_all<<<8320, 256>>>(W_c, W_cp, W_qc, W_qr, W_kc, W_v, W_kr,
                              WxT, WqT, WkvT);

    // fused c+cp+kr projection (2-term from x), cc stored single fp16
    cc_gemm<<<dim3(13, 32, 1), 256, GSM_CC>>>(xhi, xlo, WxT, kr, cc, 2048);

    // fused q + kv projections, flat-N (1-term from cc), 128x128 tiles, occ 2
    qkv_gemm<<<dim3(56, 32, 1), 256, QKV_SMEM>>>(cc, WqT, WkvT, qh, kc, vs);

    attn_mma<<<dim3(Sq / 128, Bq * Hq), 256, ATTN_SMEM>>>(qh, kc, kr, vs, out);
}

// round 16
// speedup vs baseline: 1.1326x; 1.0222x over previous
#include <cuda_runtime.h>
#include <cuda_fp16.h>
#include <math.h>
#include <stdint.h>

// Problem constants
#define Bq   2
#define Sq   2048
#define DIMq 2048
#define Hq   16
#define DKq  128
#define DRq  64
#define DCq  512
#define DCPq 1024
#define DVq  128
#define DQK  192
#define Mrows (Bq*Sq)      // 4096

// ------------------------- scratch arena (bss) ------------------------------
#define O_XHI    0ULL
#define O_XLO    16777216ULL
#define O_WXT    33554432ULL      // packed [1664][2048]: c[0,512) cp[512,1536) kr[1536,1600) pad
#define O_WQT    40370176ULL      // packed [16][192][1024] = flat [3072][1024]
#define O_WKVT   46661632ULL      // packed [16][256][512]  = flat [4096][512]
#define O_CC     50855936ULL      // cc single fp16 [4096][1536]
#define O_QH     63438848ULL      // q single [B,H,S,192]
#define O_KC     88604672ULL      // k_c single [B,H,S,128]
#define O_VS     105381888ULL     // v single [B,H,S,128]
#define O_KR     122159104ULL     // kr single [B,S,64] (shared across heads)
#define ARENA_BYTES 122683392ULL

__device__ __align__(256) char g_arena[ARENA_BYTES];

// ------------------------- helpers ------------------------------------------
__device__ __forceinline__ uint32_t smem_u32(const void* p) {
    uint32_t a;
    asm("{ .reg .u64 t; cvta.to.shared.u64 t, %1; cvt.u32.u64 %0, t; }" : "=r"(a) : "l"(p));
    return a;
}

__device__ __forceinline__ void cp16(uint32_t dst, const void* src) {
    asm volatile("cp.async.cg.shared.global [%0], [%1], 16;" :: "r"(dst), "l"(src));
}
#define CP_COMMIT() asm volatile("cp.async.commit_group;" ::: "memory")
#define CP_WAIT(n)  asm volatile("cp.async.wait_group %0;" :: "n"(n) : "memory")

__device__ __forceinline__ void ldm4(uint32_t* r, uint32_t addr) {
    asm volatile("ldmatrix.sync.aligned.m8n8.x4.shared.b16 {%0,%1,%2,%3}, [%4];"
                 : "=r"(r[0]), "=r"(r[1]), "=r"(r[2]), "=r"(r[3]) : "r"(addr));
}
__device__ __forceinline__ void ldm4t(uint32_t* r, uint32_t addr) {
    asm volatile("ldmatrix.sync.aligned.m8n8.x4.trans.shared.b16 {%0,%1,%2,%3}, [%4];"
                 : "=r"(r[0]), "=r"(r[1]), "=r"(r[2]), "=r"(r[3]) : "r"(addr));
}

__device__ __forceinline__ void mma16816(float* d, const uint32_t* a, const uint32_t* b) {
    asm volatile("mma.sync.aligned.m16n8k16.row.col.f32.f16.f16.f32 "
                 "{%0,%1,%2,%3}, {%4,%5,%6,%7}, {%8,%9}, {%0,%1,%2,%3};"
                 : "+f"(d[0]), "+f"(d[1]), "+f"(d[2]), "+f"(d[3])
                 : "r"(a[0]), "r"(a[1]), "r"(a[2]), "r"(a[3]), "r"(b[0]), "r"(b[1]));
}

__device__ __forceinline__ uint32_t packh2(float x, float y) {
    __half2 t = __floats2half2_rn(x, y);
    return *(uint32_t*)&t;
}

// ---------------------------------------------------------------------------
// split x fp32 -> fp16 hi/lo
// ---------------------------------------------------------------------------
__global__ __launch_bounds__(256)
void split_f32(const float* __restrict__ A, __half* __restrict__ hi,
               __half* __restrict__ lo)
{
    int i = blockIdx.x * 256 + threadIdx.x;
    float v = A[i];
    __half h = __float2half_rn(v);
    hi[i] = h;
    lo[i] = __float2half_rn(v - __half2float(h));
}

// ---------------------------------------------------------------------------
// One kernel for ALL weight transposes+roundings (8320 tiles of 32x32).
// ---------------------------------------------------------------------------
__device__ __forceinline__ void tr_tile(const float* __restrict__ W,
                                        __half* __restrict__ out,
                                        int K, int N, int bx, int by)
{
    __shared__ float t[32][33];
    const int k0 = by * 32, n0 = bx * 32;
    const int x = threadIdx.x & 31, y = threadIdx.x >> 5;
#pragma unroll
    for (int i = 0; i < 4; i++)
        t[y + 8*i][x] = W[(size_t)(k0 + y + 8*i) * N + n0 + x];
    __syncthreads();
#pragma unroll
    for (int i = 0; i < 4; i++)
        out[(size_t)(n0 + y + 8*i) * K + k0 + x] = __float2half_rn(t[x][y + 8*i]);
}

__global__ __launch_bounds__(256)
void tround_all(const float* __restrict__ W_c, const float* __restrict__ W_cp,
                const float* __restrict__ W_qc, const float* __restrict__ W_qr,
                const float* __restrict__ W_kc, const float* __restrict__ W_v,
                const float* __restrict__ W_kr,
                __half* __restrict__ WxT, __half* __restrict__ WqT,
                __half* __restrict__ WkvT)
{
    const int bid = blockIdx.x;
    if (bid < 1024) {                       // W_c -> WxT rows [0,512)
        tr_tile(W_c, WxT, 2048, 512, bid & 15, bid >> 4);
    } else if (bid < 3072) {                // W_cp -> WxT rows [512,1536)
        int l = bid - 1024;
        tr_tile(W_cp, WxT + (size_t)512 * 2048, 2048, 1024, l & 31, l >> 5);
    } else if (bid < 5120) {                // W_qc
        int l = bid - 3072;
        int h = l >> 7, rem = l & 127;
        tr_tile(W_qc + (size_t)h * 1024 * 128, WqT + (size_t)h * 192 * 1024,
                1024, 128, rem & 3, rem >> 2);
    } else if (bid < 6144) {                // W_qr
        int l = bid - 5120;
        int h = l >> 6, rem = l & 63;
        tr_tile(W_qr + (size_t)h * 1024 * 64, WqT + (size_t)h * 192 * 1024 + 128 * 1024,
                1024, 64, rem & 1, rem >> 1);
    } else if (bid < 7168) {                // W_kc
        int l = bid - 6144;
        int h = l >> 6, rem = l & 63;
        tr_tile(W_kc + (size_t)h * 512 * 128, WkvT + (size_t)h * 256 * 512,
                512, 128, rem & 3, rem >> 2);
    } else if (bid < 8192) {                // W_v
        int l = bid - 7168;
        int h = l >> 6, rem = l & 63;
        tr_tile(W_v + (size_t)h * 512 * 128, WkvT + (size_t)h * 256 * 512 + 128 * 512,
                512, 128, rem & 3, rem >> 2);
    } else {                                // W_kr -> WxT rows [1536,1600)
        int l = bid - 8192;
        tr_tile(W_kr, WxT + (size_t)1536 * 2048, 2048, 64, l & 1, l >> 1);
    }
}

// ---------------------------------------------------------------------------
// cc GEMM (TERMS=2): C = (Ahi+Alo) * W16. k=32 chunks, ROWB=80, 2 stages,
// occupancy 2. col<1536 -> Chi [M][1536]; 1536..1600 -> C1 [M][64].
// ---------------------------------------------------------------------------
__global__ __launch_bounds__(256, 2)
void cc_gemm(const __half* __restrict__ Ahi, const __half* __restrict__ Alo,
             const __half* __restrict__ Bw,
             __half* __restrict__ C1, __half* __restrict__ Chi, int K)
{
    constexpr int ROWB = 80;
    constexpr int ABUF = 128 * ROWB;    // 10240
    constexpr int BBUF = 128 * ROWB;
    constexpr int BUFSZ = 2 * ABUF + BBUF;
    constexpr int NFR  = 8;             // 64 cols per warp

    extern __shared__ __align__(16) char smg[];

    const int tid  = threadIdx.x;
    const int wid  = tid >> 5;
    const int lane = tid & 31;
    const int m_blk = blockIdx.y * 128;
    const int n_blk = blockIdx.x * 128;
    const int warp_m = (wid >> 1) * 32;
    const int warp_n = (wid & 1) * 64;

    const uint32_t sb = smem_u32(smg);
    const int KC = K >> 5;

    float acc[2][NFR][4];
#pragma unroll
    for (int mi = 0; mi < 2; mi++)
#pragma unroll
        for (int ni = 0; ni < NFR; ni++)
#pragma unroll
            for (int j = 0; j < 4; j++) acc[mi][ni][j] = 0.f;

    auto load_chunk = [&](int i, int buf) {
        const int kt = i << 5;
        const uint32_t db = sb + buf * BUFSZ;
#pragma unroll
        for (int j = 0; j < 2; j++) {
            int e = tid + j * 256;
            int r = e >> 2, s = e & 3;
            size_t g = (size_t)(m_blk + r) * 2048 + kt + s * 8;
            cp16(db + r * ROWB + s * 16, Ahi + g);
            cp16(db + ABUF + r * ROWB + s * 16, Alo + g);
        }
#pragma unroll
        for (int j = 0; j < 2; j++) {
            int e = tid + j * 256;
            int r = e >> 2, s = e & 3;
            cp16(db + 2 * ABUF + r * ROWB + s * 16,
                 Bw + (size_t)(n_blk + r) * K + kt + s * 8);
        }
        CP_COMMIT();
    };

    load_chunk(0, 0);

    const uint32_t aoff = (uint32_t)((warp_m + (lane & 15)) * ROWB + ((lane >> 4) << 4));
    const uint32_t boff = (uint32_t)((warp_n + (lane & 7) + ((lane >> 4) << 3)) * ROWB +
                                     (((lane >> 3) & 1) << 4));

    for (int i = 0; i < KC; i++) {
        const int buf = i & 1;
        if (i + 1 < KC) load_chunk(i + 1, buf ^ 1);
        else CP_COMMIT();
        CP_WAIT(1);
        __syncthreads();

        const uint32_t db = sb + buf * BUFSZ;
#pragma unroll
        for (int ks = 0; ks < 2; ks++) {
            uint32_t ah[2][4], al[2][4];
#pragma unroll
            for (int mi = 0; mi < 2; mi++) {
                ldm4(ah[mi], db + aoff + mi * 16 * ROWB + ks * 32);
                ldm4(al[mi], db + ABUF + aoff + mi * 16 * ROWB + ks * 32);
            }
            uint32_t b[NFR][2];
#pragma unroll
            for (int nj = 0; nj < NFR / 2; nj++) {
                uint32_t r[4];
                ldm4(r, db + 2 * ABUF + boff + nj * 16 * ROWB + ks * 32);
                b[2*nj][0] = r[0]; b[2*nj][1] = r[1];
                b[2*nj+1][0] = r[2]; b[2*nj+1][1] = r[3];
            }
#pragma unroll
            for (int mi = 0; mi < 2; mi++)
#pragma unroll
                for (int ni = 0; ni < NFR; ni++) {
                    mma16816(acc[mi][ni], ah[mi], b[ni]);
                    mma16816(acc[mi][ni], al[mi], b[ni]);
                }
        }
        __syncthreads();
    }

    const int g = lane >> 2, c2 = (lane & 3) * 2;
#pragma unroll
    for (int mi = 0; mi < 2; mi++) {
#pragma unroll
        for (int ni = 0; ni < NFR; ni++) {
            int col = n_blk + warp_n + ni * 8 + c2;
#pragma unroll
            for (int hrow = 0; hrow < 2; hrow++) {
                int m = m_blk + warp_m + mi * 16 + g + hrow * 8;
                float v0 = acc[mi][ni][hrow * 2];
                float v1 = acc[mi][ni][hrow * 2 + 1];
                if (col < 1536)
                    *(uint32_t*)(Chi + (size_t)m * 1536 + col) = packh2(v0, v1);
                else if (col < 1600)
                    *(uint32_t*)(C1 + (size_t)m * 64 + col - 1536) = packh2(v0, v1);
            }
        }
    }
}

// ---------------------------------------------------------------------------
// Fused q + kv projections, flat-N view (1-term, 128x128 CTA tile, warp tile
// 32x64, k=64 chunks, ROWB=144, 2 stages, occupancy 2).
// ---------------------------------------------------------------------------
#define QROWB 144
#define QABUF (128 * QROWB)       // 18432
#define QBUFSZ (2 * QABUF)        // 36864 (A + B)
#define QKV_SMEM (2 * QBUFSZ)     // 73728

__global__ __launch_bounds__(256, 2)
void qkv_gemm(const __half* __restrict__ cc, const __half* __restrict__ WqT,
              const __half* __restrict__ WkvT,
              __half* __restrict__ qh, __half* __restrict__ kc,
              __half* __restrict__ vs)
{
    extern __shared__ __align__(16) char smg[];

    const int xb = blockIdx.x;
    const bool isq = xb < 24;
    const int tid  = threadIdx.x;
    const int wid  = tid >> 5;
    const int lane = tid & 31;
    const int m_blk = blockIdx.y * 128;
    const int warp_m = (wid >> 1) * 32;
    const int warp_n = (wid & 1) * 64;

    const __half* Ap;
    const __half* Bp;
    int K, n_blk;
    if (isq) {
        Ap = cc + 512; K = 1024; n_blk = xb * 128;
        Bp = WqT + (size_t)n_blk * 1024;
    } else {
        Ap = cc; K = 512; n_blk = (xb - 24) * 128;
        Bp = WkvT + (size_t)n_blk * 512;
    }

    const uint32_t sb = smem_u32(smg);
    const int KC = K >> 6;

    float acc[2][8][4];
#pragma unroll
    for (int mi = 0; mi < 2; mi++)
#pragma unroll
        for (int ni = 0; ni < 8; ni++)
#pragma unroll
            for (int j = 0; j < 4; j++) acc[mi][ni][j] = 0.f;

    auto load_chunk = [&](int i, int buf) {
        const int kt = i << 6;
        const uint32_t db = sb + buf * QBUFSZ;
#pragma unroll
        for (int j = 0; j < 4; j++) {
            int e = tid + j * 256;
            int r = e >> 3, s = e & 7;
            cp16(db + r * QROWB + s * 16, Ap + (size_t)(m_blk + r) * 1536 + kt + s * 8);
        }
#pragma unroll
        for (int j = 0; j < 4; j++) {
            int e = tid + j * 256;
            int r = e >> 3, s = e & 7;
            cp16(db + QABUF + r * QROWB + s * 16, Bp + (size_t)r * K + kt + s * 8);
        }
        CP_COMMIT();
    };

    load_chunk(0, 0);

    const uint32_t aoff = (uint32_t)((warp_m + (lane & 15)) * QROWB + ((lane >> 4) << 4));
    const uint32_t boff = (uint32_t)((warp_n + (lane & 7) + ((lane >> 4) << 3)) * QROWB +
                                     (((lane >> 3) & 1) << 4));

    for (int i = 0; i < KC; i++) {
        const int buf = i & 1;
        if (i + 1 < KC) load_chunk(i + 1, buf ^ 1);
        else CP_COMMIT();
        CP_WAIT(1);
        __syncthreads();

        const uint32_t db = sb + buf * QBUFSZ;
#pragma unroll
        for (int ks = 0; ks < 4; ks++) {
            uint32_t a[2][4];
#pragma unroll
            for (int mi = 0; mi < 2; mi++)
                ldm4(a[mi], db + aoff + mi * 16 * QROWB + ks * 32);
            uint32_t b[8][2];
#pragma unroll
            for (int nj = 0; nj < 4; nj++) {
                uint32_t r[4];
                ldm4(r, db + QABUF + boff + nj * 16 * QROWB + ks * 32);
                b[2*nj][0] = r[0]; b[2*nj][1] = r[1];
                b[2*nj+1][0] = r[2]; b[2*nj+1][1] = r[3];
            }
#pragma unroll
            for (int mi = 0; mi < 2; mi++)
#pragma unroll
                for (int ni = 0; ni < 8; ni++)
                    mma16816(acc[mi][ni], a[mi], b[ni]);
        }
        __syncthreads();
    }

    const int g = lane >> 2, c2 = (lane & 3) * 2;
#pragma unroll
    for (int mi = 0; mi < 2; mi++) {
#pragma unroll
        for (int ni = 0; ni < 8; ni++) {
            int col = n_blk + warp_n + ni * 8 + c2;
#pragma unroll
            for (int hrow = 0; hrow < 2; hrow++) {
                int m = m_blk + warp_m + mi * 16 + g + hrow * 8;
                float v0 = acc[mi][ni][hrow * 2];
                float v1 = acc[mi][ni][hrow * 2 + 1];
                int b = m >> 11, s = m & 2047;
                if (isq) {
                    int head = col / 192, cin = col - head * 192;
                    size_t rowb = (size_t)((b * Hq + head) * Sq + s);
                    *(uint32_t*)(qh + rowb * DQK + cin) = packh2(v0, v1);
                } else {
                    int head = col >> 8, cin = col & 255;
                    size_t rowb = (size_t)((b * Hq + head) * Sq + s);
                    if (cin < 128)
                        *(uint32_t*)(kc + rowb * 128 + cin) = packh2(v0, v1);
                    else
                        *(uint32_t*)(vs + rowb * 128 + cin - 128) = packh2(v0, v1);
                }
            }
        }
    }
}

// ---------------------------------------------------------------------------
// Causal flash attention, fp16 operands, fp32 accum. Q fragments cached in
// registers (staged once through the K-buffer area). K tile assembled from
// per-head k_c (cols 0-127) + shared kr (cols 128-191). grid (S/128, B*H).
// ---------------------------------------------------------------------------
#define QSTRB 400   // 192 fp16 = 384 B + 16 pad (staging + K tiles)
#define VSTRB 272   // 128 fp16 = 256 B + 16 pad
#define KBUF0 0              // 2 x 25600 (K assembled); also Q staging (51200)
#define VBUF0 51200          // 2 x 17408 (V)
#define ATTN_SMEM 86016

__global__ __launch_bounds__(256, 1)
void attn_mma(const __half* __restrict__ q_,
              const __half* __restrict__ kc_, const __half* __restrict__ kr_,
              const __half* __restrict__ v_, float* __restrict__ O)
{
    extern __shared__ __align__(16) char sm[];
    const uint32_t sb = smem_u32(sm);

    const int bh = blockIdx.y;
    const int b = bh >> 4, h = bh & 15;
    const int s0 = ((int)gridDim.x - 1 - (int)blockIdx.x) * 128;
    const int tid = threadIdx.x, wid = tid >> 5, lane = tid & 31;
    const int warp_m = wid * 16;
    const int g = lane >> 2, c2 = (lane & 3) * 2;

    const size_t qb  = (size_t)bh * Sq * DQK;
    const size_t kcb = (size_t)bh * Sq * DKq;
    const size_t krb = (size_t)b * Sq * DRq;
    const size_t vb  = (size_t)bh * Sq * DVq;

    const uint32_t a_off = (uint32_t)((warp_m + (lane & 15)) * QSTRB + ((lane >> 4) << 4));
    const uint32_t b_off = (uint32_t)(((lane & 7) + ((lane >> 4) << 3)) * QSTRB +
                                      (((lane >> 3) & 1) << 4));
    const uint32_t v_off = (uint32_t)((lane & 15) * VSTRB + ((lane >> 4) << 4));

    // ---- stage Q through the K-buffer area, then cache fragments in regs ----
    uint32_t qf[12][4];
    {
        const __half* sh = q_ + qb + (size_t)s0 * DQK;
#pragma unroll
        for (int j = 0; j < 12; j++) {
            int e = tid + j * 256;            // 0..3071 = 128 rows x 24 segs
            int r = e / 24, s = e - r * 24;
            cp16(sb + KBUF0 + r * QSTRB + s * 16, sh + r * 192 + s * 8);
        }
        CP_COMMIT();
        CP_WAIT(0);
        __syncthreads();
#pragma unroll
        for (int ks = 0; ks < 12; ks++)
            ldm4(qf[ks], sb + KBUF0 + a_off + ks * 32);
        __syncthreads();   // staging area free for K(0)
    }

    // ---- K/V tile loader: K = [k_c | kr] ----
    auto load_kv = [&](int jb, int buf) {
        const uint32_t kb = sb + KBUF0 + buf * 25600;
        const uint32_t vbuf = sb + VBUF0 + buf * 17408;
        const __half* skc = kc_ + kcb + (size_t)(jb * 64) * DKq;
        const __half* skr = kr_ + krb + (size_t)(jb * 64) * DRq;
        const __half* sv  = v_ + vb + (size_t)(jb * 64) * DVq;
#pragma unroll
        for (int j = 0; j < 6; j++) {
            int e = tid + j * 256;            // 0..1535 = 64 rows x 24 segs
            int r = e / 24, s = e - r * 24;
            if (s < 16)
                cp16(kb + r * QSTRB + s * 16, skc + r * 128 + s * 8);
            else
                cp16(kb + r * QSTRB + s * 16, skr + r * 64 + (s - 16) * 8);
        }
#pragma unroll
        for (int j = 0; j < 4; j++) {
            int e = tid + j * 256;            // 0..1023
            int r = e >> 4, s = e & 15;
            cp16(vbuf + r * VSTRB + s * 16, sv + r * 128 + s * 8);
        }
        CP_COMMIT();
    };

    const int jmax = (s0 >> 6) + 1;
    load_kv(0, 0);

    float accO[16][4];
#pragma unroll
    for (int nf = 0; nf < 16; nf++)
#pragma unroll
        for (int j = 0; j < 4; j++) accO[nf][j] = 0.f;
    float m0 = -INFINITY, m1 = -INFINITY, l0 = 0.f, l1 = 0.f;

    const float scale = 0.07216878364870322f;   // 1/sqrt(192)
    const int row0 = s0 + warp_m + g;
    const int row1 = row0 + 8;

    for (int jb = 0; jb <= jmax; jb++) {
        const int buf = jb & 1;
        if (jb < jmax) {
            load_kv(jb + 1, buf ^ 1);
            CP_WAIT(1);
        } else {
            CP_WAIT(0);
        }
        __syncthreads();

        const uint32_t kb = sb + KBUF0 + buf * 25600;
        const uint32_t vbuf = sb + VBUF0 + buf * 17408;

        // ---- S = Q K^T (Q from registers) ----
        float S[8][4];
#pragma unroll
        for (int nf = 0; nf < 8; nf++)
#pragma unroll
            for (int j = 0; j < 4; j++) S[nf][j] = 0.f;

#pragma unroll
        for (int ks = 0; ks < 12; ks++) {
#pragma unroll
            for (int p = 0; p < 4; p++) {
                uint32_t bv[4];
                ldm4(bv, kb + b_off + p * 16 * QSTRB + ks * 32);
                mma16816(S[2*p],   qf[ks], bv);
                mma16816(S[2*p+1], qf[ks], bv + 2);
            }
        }

        // ---- scale + causal mask ----
        const bool domask = ((jb << 6) + 63) > row0;
#pragma unroll
        for (int nf = 0; nf < 8; nf++) {
#pragma unroll
            for (int j = 0; j < 4; j++) S[nf][j] *= scale;
            if (domask) {
                int key0 = (jb << 6) + nf * 8 + c2;
                if (key0     > row0) S[nf][0] = -INFINITY;
                if (key0 + 1 > row0) S[nf][1] = -INFINITY;
                if (key0     > row1) S[nf][2] = -INFINITY;
                if (key0 + 1 > row1) S[nf][3] = -INFINITY;
            }
        }

        // ---- online softmax ----
        float rm0 = -INFINITY, rm1 = -INFINITY;
#pragma unroll
        for (int nf = 0; nf < 8; nf++) {
            rm0 = fmaxf(rm0, fmaxf(S[nf][0], S[nf][1]));
            rm1 = fmaxf(rm1, fmaxf(S[nf][2], S[nf][3]));
        }
        rm0 = fmaxf(rm0, __shfl_xor_sync(0xffffffffu, rm0, 1));
        rm0 = fmaxf(rm0, __shfl_xor_sync(0xffffffffu, rm0, 2));
        rm1 = fmaxf(rm1, __shfl_xor_sync(0xffffffffu, rm1, 1));
        rm1 = fmaxf(rm1, __shfl_xor_sync(0xffffffffu, rm1, 2));

        float mn0 = fmaxf(m0, rm0), mn1 = fmaxf(m1, rm1);
        float al0 = __expf(m0 - mn0), al1 = __expf(m1 - mn1);
        m0 = mn0; m1 = mn1;

        float rs0 = 0.f, rs1 = 0.f;
#pragma unroll
        for (int nf = 0; nf < 8; nf++) {
            S[nf][0] = __expf(S[nf][0] - mn0);
            S[nf][1] = __expf(S[nf][1] - mn0);
            S[nf][2] = __expf(S[nf][2] - mn1);
            S[nf][3] = __expf(S[nf][3] - mn1);
            rs0 += S[nf][0] + S[nf][1];
            rs1 += S[nf][2] + S[nf][3];
        }
        rs0 += __shfl_xor_sync(0xffffffffu, rs0, 1);
        rs0 += __shfl_xor_sync(0xffffffffu, rs0, 2);
        rs1 += __shfl_xor_sync(0xffffffffu, rs1, 1);
        rs1 += __shfl_xor_sync(0xffffffffu, rs1, 2);
        l0 = l0 * al0 + rs0;
        l1 = l1 * al1 + rs1;

#pragma unroll
        for (int nf = 0; nf < 16; nf++) {
            accO[nf][0] *= al0; accO[nf][1] *= al0;
            accO[nf][2] *= al1; accO[nf][3] *= al1;
        }

        // ---- pack P fragments (single fp16) ----
        uint32_t ph[4][4];
#pragma unroll
        for (int t = 0; t < 4; t++) {
            ph[t][0] = packh2(S[2*t][0],   S[2*t][1]);
            ph[t][1] = packh2(S[2*t][2],   S[2*t][3]);
            ph[t][2] = packh2(S[2*t+1][0], S[2*t+1][1]);
            ph[t][3] = packh2(S[2*t+1][2], S[2*t+1][3]);
        }

        // ---- O += P V ----
#pragma unroll
        for (int t = 0; t < 4; t++) {
#pragma unroll
            for (int p = 0; p < 8; p++) {
                uint32_t bv[4];
                ldm4t(bv, vbuf + v_off + t * 16 * VSTRB + p * 32);
                mma16816(accO[2*p],   ph[t], bv);
                mma16816(accO[2*p+1], ph[t], bv + 2);
            }
        }
        __syncthreads();
    }

    // ---- epilogue ----
    float inv0 = 1.0f / l0, inv1 = 1.0f / l1;
#pragma unroll
    for (int nf = 0; nf < 16; nf++) {
        int col = h * DVq + nf * 8 + c2;
        size_t o0 = ((size_t)(b * Sq + row0)) * (size_t)(Hq * DVq) + col;
        size_t o1 = ((size_t)(b * Sq + row1)) * (size_t)(Hq * DVq) + col;
        *(float2*)(O + o0) = make_float2(accO[nf][0] * inv0, accO[nf][1] * inv0);
        *(float2*)(O + o1) = make_float2(accO[nf][2] * inv1, accO[nf][3] * inv1);
    }
}

// ---------------------------------------------------------------------------
extern "C" void kernel_launch(void* const* d_in, const int* in_sizes, int n_in,
                              void* d_out, int out_size)
{
    (void)in_sizes; (void)n_in; (void)out_size;
    const float* x    = (const float*)d_in[0];
    const float* W_c  = (const float*)d_in[1];
    const float* W_cp = (const float*)d_in[2];
    const float* W_qc = (const float*)d_in[3];
    const float* W_qr = (const float*)d_in[4];
    const float* W_kc = (const float*)d_in[5];
    const float* W_kr = (const float*)d_in[6];
    const float* W_v  = (const float*)d_in[7];
    float* out = (float*)d_out;

    char* arena;
    cudaGetSymbolAddress((void**)&arena, g_arena);
    __half* xhi   = (__half*)(arena + O_XHI);
    __half* xlo   = (__half*)(arena + O_XLO);
    __half* WxT   = (__half*)(arena + O_WXT);
    __half* WqT   = (__half*)(arena + O_WQT);
    __half* WkvT  = (__half*)(arena + O_WKVT);
    __half* cc    = (__half*)(arena + O_CC);
    __half* qh    = (__half*)(arena + O_QH);
    __half* kc    = (__half*)(arena + O_KC);
    __half* vs    = (__half*)(arena + O_VS);
    __half* kr    = (__half*)(arena + O_KR);

    const int GSM_CC = 2 * (2 * 10240 + 128 * 80);  // 61440
    cudaFuncSetAttribute(cc_gemm, cudaFuncAttributeMaxDynamicSharedMemorySize, GSM_CC);
    cudaFuncSetAttribute(qkv_gemm, cudaFuncAttributeMaxDynamicSharedMemorySize, QKV_SMEM);
    cudaFuncSetAttribute(attn_mma, cudaFuncAttributeMaxDynamicSharedMemorySize, ATTN_SMEM);

    // prep: x split + all weight transposes in one kernel
    split_f32<<<32768, 256>>>(x, xhi, xlo);
    tround_all<<<8320, 256>>>(W_c, W_cp, W_qc, W_qr, W_kc, W_v, W_kr,
                              WxT, WqT, WkvT);

    // fused c+cp+kr projection (2-term from x), cc stored single fp16
    cc_gemm<<<dim3(13, 32, 1), 256, GSM_CC>>>(xhi, xlo, WxT, kr, cc, 2048);

    // fused q + kv projections, flat-N (1-term from cc), 128x128 tiles, occ 2
    qkv_gemm<<<dim3(56, 32, 1), 256, QKV_SMEM>>>(cc, WqT, WkvT, qh, kc, vs);

    attn_mma<<<dim3(Sq / 128, Bq * Hq), 256, ATTN_SMEM>>>(qh, kc, kr, vs, out);
}